// round 6
// baseline (speedup 1.0000x reference)
#include <cuda_runtime.h>
#include <cuda_bf16.h>
#include <cstdint>
#include <math.h>

// Problem constants
#define B_    4
#define SQ_   1024
#define SKV_  4096
#define DQ_   1024
#define DKV_  768
#define H_    16
#define DH_   64
#define DOUT_ 256

#define SWZ(o) ((o) ^ (((o) >> 3) & 0x70))

// ---------------------------------------------------------------------------
// Scratch (static device globals; bf16 buffers 16B aligned for cp.async)
// ---------------------------------------------------------------------------
#define AL16 __align__(16)
// raw-input splits
__device__ AL16 __nv_bfloat16 g_sqh[(size_t)B_ * SQ_  * DQ_ ], g_sql[(size_t)B_ * SQ_  * DQ_ ];
__device__ AL16 __nv_bfloat16 g_skh[(size_t)B_ * SKV_ * DKV_], g_skl[(size_t)B_ * SKV_ * DKV_];
__device__ AL16 __nv_bfloat16 g_svh[(size_t)B_ * SKV_ * DKV_], g_svl[(size_t)B_ * SKV_ * DKV_];
// weight splits
__device__ AL16 __nv_bfloat16 g_wqh[DQ_ * DQ_ ],  g_wql[DQ_ * DQ_ ];
__device__ AL16 __nv_bfloat16 g_wkh[DQ_ * DKV_],  g_wkl[DQ_ * DKV_];
__device__ AL16 __nv_bfloat16 g_wvh[DQ_ * DKV_],  g_wvl[DQ_ * DKV_];
__device__ AL16 __nv_bfloat16 g_woh[DOUT_ * DQ_], g_wol[DOUT_ * DQ_];
// projected tensors (bf16 hi/lo)
__device__ AL16 __nv_bfloat16 g_qh [(size_t)B_ * SQ_  * DQ_], g_ql [(size_t)B_ * SQ_  * DQ_];
__device__ AL16 __nv_bfloat16 g_kh [(size_t)B_ * SKV_ * DQ_], g_kl [(size_t)B_ * SKV_ * DQ_];
__device__ AL16 __nv_bfloat16 g_vh [(size_t)B_ * SKV_ * DQ_], g_vl [(size_t)B_ * SKV_ * DQ_];
__device__ AL16 __nv_bfloat16 g_vth[(size_t)B_ * DQ_ * SKV_], g_vtl[(size_t)B_ * DQ_ * SKV_];
// softmax weights (bf16 hi/lo) for PV
__device__ AL16 __nv_bfloat16 g_wth[(size_t)B_ * H_ * SQ_ * SKV_];
__device__ AL16 __nv_bfloat16 g_wtl[(size_t)B_ * H_ * SQ_ * SKV_];
// attention output pre-Wo (bf16 hi/lo)
__device__ AL16 __nv_bfloat16 g_ath[(size_t)B_ * SQ_ * DQ_], g_atl[(size_t)B_ * SQ_ * DQ_];
__device__ int g_mask_flag;

// ---------------------------------------------------------------------------
// Mask dtype probe
// ---------------------------------------------------------------------------
__global__ void probe_mask_kernel(const unsigned int* __restrict__ m)
{
    if (blockIdx.x != 0 || threadIdx.x != 0) return;
    int is_i32 = 1, is_f32 = 1;
    for (int i = 0; i < 4096; i++) {
        unsigned v = m[i];
        if (v > 1u) is_i32 = 0;
        if (v != 0u && v != 0x3F800000u) is_f32 = 0;
    }
    g_mask_flag = is_i32 ? 1 : (is_f32 ? 2 : 0);
}

__device__ __forceinline__ bool read_mask(const void* m, long i, int flag)
{
    if (flag == 1) return ((const int*)m)[i] != 0;
    if (flag == 2) return ((const float*)m)[i] != 0.0f;
    return ((const unsigned char*)m)[i] != 0;
}

// ---------------------------------------------------------------------------
// Primitives
// ---------------------------------------------------------------------------
__device__ __forceinline__ uint32_t smem_to_u32(const void* p) {
    uint32_t a;
    asm("{ .reg .u64 t; cvta.to.shared.u64 t, %1; cvt.u32.u64 %0, t; }"
        : "=r"(a) : "l"(p));
    return a;
}

__device__ __forceinline__ void ldm_x4(uint32_t addr, uint32_t* r) {
    asm volatile("ldmatrix.sync.aligned.m8n8.x4.shared.b16 {%0,%1,%2,%3}, [%4];"
                 : "=r"(r[0]), "=r"(r[1]), "=r"(r[2]), "=r"(r[3]) : "r"(addr));
}

__device__ __forceinline__ void mma_bf16(float* d, const uint32_t* a,
                                         uint32_t b0, uint32_t b1) {
    asm volatile(
        "mma.sync.aligned.m16n8k16.row.col.f32.bf16.bf16.f32 "
        "{%0,%1,%2,%3}, {%4,%5,%6,%7}, {%8,%9}, {%0,%1,%2,%3};"
        : "+f"(d[0]), "+f"(d[1]), "+f"(d[2]), "+f"(d[3])
        : "r"(a[0]), "r"(a[1]), "r"(a[2]), "r"(a[3]), "r"(b0), "r"(b1));
}

__device__ __forceinline__ uint32_t pk2(__nv_bfloat16 a, __nv_bfloat16 b)
{
    return (uint32_t)__bfloat16_as_ushort(a) | ((uint32_t)__bfloat16_as_ushort(b) << 16);
}

// cp.async a ROWSx64-bf16 tile (rows of 128B) into SW128 swizzled smem
template<int ROWS>
__device__ __forceinline__ void cpa_tile(uint32_t dst, const __nv_bfloat16* src,
                                         int ld, int tid)
{
#pragma unroll
    for (int i = 0; i < ROWS / 32; i++) {
        int f = tid + i * 256;
        int r = f >> 3, c = f & 7;
        uint32_t d = dst + SWZ((unsigned)(r * 128 + c * 16));
        const void* s = src + (long)r * ld + c * 8;
        asm volatile("cp.async.cg.shared.global [%0], [%1], 16;" :: "r"(d), "l"(s));
    }
}

// ---------------------------------------------------------------------------
// fp32 -> bf16 hi/lo split (elementwise, n divisible by 1024)
// ---------------------------------------------------------------------------
__global__ __launch_bounds__(256)
void split_kernel(const float* __restrict__ src,
                  __nv_bfloat16* __restrict__ h, __nv_bfloat16* __restrict__ l)
{
    long i = ((long)blockIdx.x * 256 + threadIdx.x) * 4;
    float4 v = *(const float4*)(src + i);
    __nv_bfloat16 h0 = __float2bfloat16(v.x), h1 = __float2bfloat16(v.y);
    __nv_bfloat16 h2 = __float2bfloat16(v.z), h3 = __float2bfloat16(v.w);
    *(uint2*)(h + i) = make_uint2(pk2(h0, h1), pk2(h2, h3));
    *(uint2*)(l + i) = make_uint2(
        pk2(__float2bfloat16(v.x - __bfloat162float(h0)),
            __float2bfloat16(v.y - __bfloat162float(h1))),
        pk2(__float2bfloat16(v.z - __bfloat162float(h2)),
            __float2bfloat16(v.w - __bfloat162float(h3))));
}

// ---------------------------------------------------------------------------
// bf16 hi/lo GEMM via HMMA.  D[128, 64] per CTA = A[128,K] @ B[64,K]^T
// MODE 0: projections: generic A/B, epi = +bias, write bf16 h/l
// MODE 1: scores per z=(b,h): epi = mask ? -1e9 : *0.125, write fp32
// MODE 2: PV per z=(b,h): A=Wt h/l, B=vt h/l, epi = write bf16 h/l
// MODE 3: Wo: generic A/B, epi = +bias, write fp32
// ---------------------------------------------------------------------------
template<int MODE>
__global__ void __launch_bounds__(256, 1)
hgemm_kernel(const __nv_bfloat16* __restrict__ Ah, const __nv_bfloat16* __restrict__ Al, int lda,
             const __nv_bfloat16* __restrict__ Bh, const __nv_bfloat16* __restrict__ Bl, int ldb,
             const float* __restrict__ bias,
             void* __restrict__ C0, void* __restrict__ C1, int ldc,
             int Kdim, const void* __restrict__ mask)
{
    extern __shared__ char smem[];
    constexpr int NT = 64;
    constexpr int NF = NT / 16;                      // 4
    constexpr unsigned MASKSZ = (MODE == 1) ? (unsigned)(NT * 128) : 0u;
    constexpr unsigned ABYTES = 128 * 128;
    constexpr unsigned BBYTES = NT * 128;
    constexpr unsigned BUFSZ  = 2 * ABYTES + 2 * BBYTES;   // 49152

    const uint32_t sbase = smem_to_u32(smem);
    const int tid = threadIdx.x;
    const int wid = tid >> 5, lid = tid & 31;
    const int wm = wid & 3, wn = wid >> 2;           // 4(m) x 2(n)
    const int m0 = blockIdx.y * 128, n0 = blockIdx.x * NT, z = blockIdx.z;

    const __nv_bfloat16 *Aph, *Apl, *Bph, *Bpl;
    int LDA, LDB, LDC;
    char* Cp0; char* Cp1;
    if (MODE == 0 || MODE == 3) {
        Aph = Ah + (long)m0 * lda;  Apl = Al + (long)m0 * lda;  LDA = lda;
        Bph = Bh + (long)n0 * ldb;  Bpl = Bl + (long)n0 * ldb;  LDB = ldb;
        LDC = ldc;
        long co = (long)m0 * ldc + n0;
        if (MODE == 0) { Cp0 = (char*)((__nv_bfloat16*)C0 + co); Cp1 = (char*)((__nv_bfloat16*)C1 + co); }
        else           { Cp0 = (char*)((float*)C0 + co);         Cp1 = nullptr; }
    } else if (MODE == 1) {
        int b = z >> 4, h = z & 15;
        long ao = ((long)b * SQ_  + m0) * DQ_ + h * DH_;
        long bo = ((long)b * SKV_ + n0) * DQ_ + h * DH_;
        Aph = Ah + ao; Apl = Al + ao; LDA = DQ_;
        Bph = Bh + bo; Bpl = Bl + bo; LDB = DQ_;
        LDC = SKV_;
        Cp0 = (char*)((float*)C0 + ((long)z * SQ_ + m0) * SKV_ + n0);
        Cp1 = nullptr;
    } else {
        int b = z >> 4, h = z & 15;
        long ao = ((long)z * SQ_ + m0) * SKV_;
        long bo = ((long)(b * DQ_ + h * DH_)) * SKV_;
        Aph = Ah + ao; Apl = Al + ao; LDA = SKV_;
        Bph = Bh + bo; Bpl = Bl + bo; LDB = SKV_;
        LDC = DQ_;
        long co = ((long)b * SQ_ + m0) * DQ_ + h * DH_;
        Cp0 = (char*)((__nv_bfloat16*)C0 + co); Cp1 = (char*)((__nv_bfloat16*)C1 + co);
    }

    // mask tile -> smem u8 [kv NT][q 128] (scores only)
    if (MODE == 1) {
        const int flag = g_mask_flag;
        const int b = z >> 4;
        for (int i = tid; i < NT * 128; i += 256) {
            int kv = i >> 7, q = i & 127;
            bool mm = read_mask(mask, ((long)b * SKV_ + n0 + kv) * SQ_ + m0 + q, flag);
            smem[i] = mm ? 1 : 0;
        }
    }

    float dc[2 * NF][4];
#pragma unroll
    for (int i = 0; i < 2 * NF; i++)
#pragma unroll
        for (int j = 0; j < 4; j++) dc[i][j] = 0.0f;

    const int ns = Kdim >> 6;

    auto issue = [&](int s) {
        uint32_t base = sbase + MASKSZ + (unsigned)(s & 1) * BUFSZ;
        cpa_tile<128>(base,                   Aph + (long)s * 64, LDA, tid);
        cpa_tile<128>(base + ABYTES,          Apl + (long)s * 64, LDA, tid);
        cpa_tile<NT> (base + 2 * ABYTES,          Bph + (long)s * 64, LDB, tid);
        cpa_tile<NT> (base + 2 * ABYTES + BBYTES, Bpl + (long)s * 64, LDB, tid);
        asm volatile("cp.async.commit_group;" ::: "memory");
    };

    auto compute = [&](int buf) {
        const uint32_t sA  = sbase + MASKSZ + (unsigned)buf * BUFSZ;
        const uint32_t sAl = sA + ABYTES;
        const uint32_t sB  = sA + 2 * ABYTES;
        const uint32_t sBl = sB + BBYTES;
        const int lr = lid & 15, hsel = (lid >> 4) << 4;
#pragma unroll
        for (int ks = 0; ks < 4; ks++) {
            const int kb = ks * 32 + hsel;
            uint32_t aH[2][4], aL[2][4];
#pragma unroll
            for (int i = 0; i < 2; i++) {
                unsigned off = SWZ((unsigned)((wm * 32 + i * 16 + lr) * 128 + kb));
                ldm_x4(sA + off, aH[i]);
                ldm_x4(sAl + off, aL[i]);
            }
#pragma unroll
            for (int jj = 0; jj < NF / 2; jj++) {
                unsigned off = SWZ((unsigned)((wn * 32 + jj * 16 + lr) * 128 + kb));
                uint32_t bH[4], bL[4];
                ldm_x4(sB + off, bH);
                ldm_x4(sBl + off, bL);
#pragma unroll
                for (int i = 0; i < 2; i++) {
#pragma unroll
                    for (int t = 0; t < 2; t++) {
                        float* d = dc[i * NF + jj * 2 + t];
                        mma_bf16(d, aH[i], bH[t], bH[t + 2]);
                        mma_bf16(d, aH[i], bL[t], bL[t + 2]);
                        mma_bf16(d, aL[i], bH[t], bH[t + 2]);
                    }
                }
            }
        }
    };

    issue(0);
    for (int s = 0; s < ns; s++) {
        if (s + 1 < ns) {
            issue(s + 1);
            asm volatile("cp.async.wait_group 1;" ::: "memory");
        } else {
            asm volatile("cp.async.wait_group 0;" ::: "memory");
        }
        __syncthreads();
        compute(s & 1);
        __syncthreads();
    }

    // ---- epilogue ----
#pragma unroll
    for (int i = 0; i < 2; i++) {
#pragma unroll
        for (int f = 0; f < NF; f++) {
            const float* d = dc[i * NF + f];
            int rl = wm * 32 + i * 16 + (lid >> 2);
            int cl = wn * 32 + f * 8 + ((lid & 3) << 1);
            if (MODE == 0 || MODE == 2) {
                float bx = 0.0f, by = 0.0f;
                if (MODE == 0) { float2 bb = *(const float2*)(bias + n0 + cl); bx = bb.x; by = bb.y; }
                float v0 = d[0] + bx, v1 = d[1] + by;
                float v2 = d[2] + bx, v3 = d[3] + by;
                __nv_bfloat16 h0 = __float2bfloat16(v0), h1 = __float2bfloat16(v1);
                __nv_bfloat16 h2 = __float2bfloat16(v2), h3 = __float2bfloat16(v3);
                __nv_bfloat16* ch = (__nv_bfloat16*)Cp0;
                __nv_bfloat16* cll = (__nv_bfloat16*)Cp1;
                *(uint32_t*)(ch + (long)rl * LDC + cl)       = pk2(h0, h1);
                *(uint32_t*)(ch + (long)(rl + 8) * LDC + cl) = pk2(h2, h3);
                *(uint32_t*)(cll + (long)rl * LDC + cl) =
                    pk2(__float2bfloat16(v0 - __bfloat162float(h0)),
                        __float2bfloat16(v1 - __bfloat162float(h1)));
                *(uint32_t*)(cll + (long)(rl + 8) * LDC + cl) =
                    pk2(__float2bfloat16(v2 - __bfloat162float(h2)),
                        __float2bfloat16(v3 - __bfloat162float(h3)));
            } else if (MODE == 1) {
                const unsigned char* mk = (const unsigned char*)smem;
                float* cp = (float*)Cp0;
                float2 o0, o1;
                o0.x = mk[(cl + 0) * 128 + rl]     ? -1.0e9f : d[0] * 0.125f;
                o0.y = mk[(cl + 1) * 128 + rl]     ? -1.0e9f : d[1] * 0.125f;
                o1.x = mk[(cl + 0) * 128 + rl + 8] ? -1.0e9f : d[2] * 0.125f;
                o1.y = mk[(cl + 1) * 128 + rl + 8] ? -1.0e9f : d[3] * 0.125f;
                *(float2*)(cp + (long)rl * LDC + cl) = o0;
                *(float2*)(cp + (long)(rl + 8) * LDC + cl) = o1;
            } else {
                float2 bb = *(const float2*)(bias + n0 + cl);
                float* cp = (float*)Cp0;
                *(float2*)(cp + (long)rl * LDC + cl) =
                    make_float2(d[0] + bb.x, d[1] + bb.y);
                *(float2*)(cp + (long)(rl + 8) * LDC + cl) =
                    make_float2(d[2] + bb.x, d[3] + bb.y);
            }
        }
    }
}

// ---------------------------------------------------------------------------
// bf16 transpose: v h/l [b][kv][ch] -> vt h/l [b][ch][kv]
// ---------------------------------------------------------------------------
__global__ __launch_bounds__(256)
void transpose_bf16_kernel(const __nv_bfloat16* __restrict__ vh,
                           const __nv_bfloat16* __restrict__ vl,
                           __nv_bfloat16* __restrict__ vth,
                           __nv_bfloat16* __restrict__ vtl)
{
    __shared__ __nv_bfloat16 th[32][34], tl[32][34];
    const int b   = blockIdx.z;
    const int kv0 = blockIdx.x * 32, ch0 = blockIdx.y * 32;
    const int x = threadIdx.x, y = threadIdx.y;      // 32 x 8
#pragma unroll
    for (int i = y; i < 32; i += 8) {
        long src = ((long)b * SKV_ + kv0 + i) * DQ_ + ch0 + x;
        th[i][x] = vh[src];
        tl[i][x] = vl[src];
    }
    __syncthreads();
#pragma unroll
    for (int i = y; i < 32; i += 8) {
        long dst = ((long)b * DQ_ + ch0 + i) * SKV_ + kv0 + x;
        vth[dst] = th[x][i];
        vtl[dst] = tl[x][i];
    }
}

// ---------------------------------------------------------------------------
// Row softmax over SKV=4096 in place; also emit bf16 hi/lo copy for PV
// ---------------------------------------------------------------------------
__global__ __launch_bounds__(256)
void softmax_kernel(float* __restrict__ Wt,
                    __nv_bfloat16* __restrict__ wh, __nv_bfloat16* __restrict__ wl)
{
    __shared__ float shm[8];
    __shared__ float shs[8];
    __shared__ float bmx, bsum;

    const long row = blockIdx.x;
    float* p = Wt + row * SKV_;
    const int tid  = threadIdx.x;
    const int lane = tid & 31;
    const int wrp  = tid >> 5;

    float s[16];
    float mx = -3.4e38f;
#pragma unroll
    for (int i = 0; i < 16; i++) {
        s[i] = p[tid + (i << 8)];
        mx = fmaxf(mx, s[i]);
    }
#pragma unroll
    for (int o = 16; o; o >>= 1) mx = fmaxf(mx, __shfl_xor_sync(0xFFFFFFFFu, mx, o));
    if (lane == 0) shm[wrp] = mx;
    __syncthreads();
    if (tid == 0) {
        float v = shm[0];
#pragma unroll
        for (int i = 1; i < 8; i++) v = fmaxf(v, shm[i]);
        bmx = v;
    }
    __syncthreads();
    mx = bmx;

    float sum = 0.0f;
#pragma unroll
    for (int i = 0; i < 16; i++) {
        s[i] = __expf(s[i] - mx);
        sum += s[i];
    }
#pragma unroll
    for (int o = 16; o; o >>= 1) sum += __shfl_xor_sync(0xFFFFFFFFu, sum, o);
    if (lane == 0) shs[wrp] = sum;
    __syncthreads();
    if (tid == 0) {
        float v = shs[0];
#pragma unroll
        for (int i = 1; i < 8; i++) v += shs[i];
        bsum = v;
    }
    __syncthreads();
    const float inv = 1.0f / bsum;

    __nv_bfloat16* ph = wh + row * SKV_;
    __nv_bfloat16* pl = wl + row * SKV_;
#pragma unroll
    for (int i = 0; i < 16; i++) {
        int idx = tid + (i << 8);
        float v = s[i] * inv;
        p[idx] = v;
        __nv_bfloat16 h = __float2bfloat16(v);
        ph[idx] = h;
        pl[idx] = __float2bfloat16(v - __bfloat162float(h));
    }
}

// ---------------------------------------------------------------------------
// Launch
// ---------------------------------------------------------------------------
extern "C" void kernel_launch(void* const* d_in, const int* in_sizes, int n_in,
                              void* d_out, int out_size)
{
    (void)in_sizes; (void)n_in; (void)out_size;

    const float* Q   = (const float*)d_in[0];
    const float* K   = (const float*)d_in[1];
    const float* V   = (const float*)d_in[2];
    const void*  Msk = d_in[3];
    const float* Wq  = (const float*)d_in[4];
    const float* bq  = (const float*)d_in[5];
    const float* Wk  = (const float*)d_in[6];
    const float* bk  = (const float*)d_in[7];
    const float* Wv  = (const float*)d_in[8];
    const float* bv  = (const float*)d_in[9];
    const float* Wo  = (const float*)d_in[10];
    const float* bo  = (const float*)d_in[11];

    float* out = (float*)d_out;                       // [B,SQ,DOUT]
    float* Wt  = out + (size_t)B_ * SQ_ * DOUT_;      // [B,H,SQ,SKV]

    __nv_bfloat16 *sqh, *sql, *skh, *skl, *svh, *svl;
    __nv_bfloat16 *wqh, *wql, *wkh, *wkl, *wvh, *wvl, *woh, *wol;
    __nv_bfloat16 *qh, *ql, *kh, *kl, *vh, *vl, *vth, *vtl, *wth, *wtl, *ath, *atl;
    cudaGetSymbolAddress((void**)&sqh, g_sqh); cudaGetSymbolAddress((void**)&sql, g_sql);
    cudaGetSymbolAddress((void**)&skh, g_skh); cudaGetSymbolAddress((void**)&skl, g_skl);
    cudaGetSymbolAddress((void**)&svh, g_svh); cudaGetSymbolAddress((void**)&svl, g_svl);
    cudaGetSymbolAddress((void**)&wqh, g_wqh); cudaGetSymbolAddress((void**)&wql, g_wql);
    cudaGetSymbolAddress((void**)&wkh, g_wkh); cudaGetSymbolAddress((void**)&wkl, g_wkl);
    cudaGetSymbolAddress((void**)&wvh, g_wvh); cudaGetSymbolAddress((void**)&wvl, g_wvl);
    cudaGetSymbolAddress((void**)&woh, g_woh); cudaGetSymbolAddress((void**)&wol, g_wol);
    cudaGetSymbolAddress((void**)&qh,  g_qh);  cudaGetSymbolAddress((void**)&ql,  g_ql);
    cudaGetSymbolAddress((void**)&kh,  g_kh);  cudaGetSymbolAddress((void**)&kl,  g_kl);
    cudaGetSymbolAddress((void**)&vh,  g_vh);  cudaGetSymbolAddress((void**)&vl,  g_vl);
    cudaGetSymbolAddress((void**)&vth, g_vth); cudaGetSymbolAddress((void**)&vtl, g_vtl);
    cudaGetSymbolAddress((void**)&wth, g_wth); cudaGetSymbolAddress((void**)&wtl, g_wtl);
    cudaGetSymbolAddress((void**)&ath, g_ath); cudaGetSymbolAddress((void**)&atl, g_atl);

    const int SMG = 2 * 49152;            // 98304: modes 0,2,3
    const int SM1 = 8192 + 49152;         // 57344: mode 1 (mask + 1 buf)
    cudaFuncSetAttribute(hgemm_kernel<0>, cudaFuncAttributeMaxDynamicSharedMemorySize, SMG);
    cudaFuncSetAttribute(hgemm_kernel<1>, cudaFuncAttributeMaxDynamicSharedMemorySize, SM1);
    cudaFuncSetAttribute(hgemm_kernel<2>, cudaFuncAttributeMaxDynamicSharedMemorySize, SMG);
    cudaFuncSetAttribute(hgemm_kernel<3>, cudaFuncAttributeMaxDynamicSharedMemorySize, SMG);

    // 0) probe + operand splits
    probe_mask_kernel<<<1, 1>>>((const unsigned int*)Msk);
    split_kernel<<<(B_ * SQ_ * DQ_)  / 1024, 256>>>(Q,  sqh, sql);
    split_kernel<<<(B_ * SKV_ * DKV_) / 1024, 256>>>(K, skh, skl);
    split_kernel<<<(B_ * SKV_ * DKV_) / 1024, 256>>>(V, svh, svl);
    split_kernel<<<(DQ_ * DQ_)   / 1024, 256>>>(Wq, wqh, wql);
    split_kernel<<<(DQ_ * DKV_)  / 1024, 256>>>(Wk, wkh, wkl);
    split_kernel<<<(DQ_ * DKV_)  / 1024, 256>>>(Wv, wvh, wvl);
    split_kernel<<<(DOUT_ * DQ_) / 1024, 256>>>(Wo, woh, wol);

    // 1) projections -> bf16 h/l
    hgemm_kernel<0><<<dim3(DQ_ / 64, (B_ * SQ_) / 128, 1), 256, SMG>>>(
        sqh, sql, DQ_, wqh, wql, DQ_, bq, qh, ql, DQ_, DQ_, nullptr);
    hgemm_kernel<0><<<dim3(DQ_ / 64, (B_ * SKV_) / 128, 1), 256, SMG>>>(
        skh, skl, DKV_, wkh, wkl, DKV_, bk, kh, kl, DQ_, DKV_, nullptr);
    hgemm_kernel<0><<<dim3(DQ_ / 64, (B_ * SKV_) / 128, 1), 256, SMG>>>(
        svh, svl, DKV_, wvh, wvl, DKV_, bv, vh, vl, DQ_, DKV_, nullptr);

    // 1b) transpose projected V (bf16 h/l)
    transpose_bf16_kernel<<<dim3(SKV_ / 32, DQ_ / 32, B_), dim3(32, 8)>>>(
        vh, vl, vth, vtl);

    // 2) masked scores -> fp32 weights region of d_out
    hgemm_kernel<1><<<dim3(SKV_ / 64, SQ_ / 128, B_ * H_), 256, SM1>>>(
        qh, ql, 0, kh, kl, 0, nullptr, Wt, nullptr, 0, DH_, Msk);

    // 3) softmax in place + bf16 h/l copy for PV
    softmax_kernel<<<B_ * H_ * SQ_, 256>>>(Wt, wth, wtl);

    // 4) PV -> att bf16 h/l
    hgemm_kernel<2><<<dim3(1, SQ_ / 128, B_ * H_), 256, SMG>>>(
        wth, wtl, 0, vth, vtl, 0, nullptr, ath, atl, 0, SKV_, nullptr);

    // 5) output projection -> fp32 front of d_out
    hgemm_kernel<3><<<dim3(DOUT_ / 64, (B_ * SQ_) / 128, 1), 256, SMG>>>(
        ath, atl, DQ_, woh, wol, DQ_, bo, out, nullptr, DOUT_, DQ_, nullptr);
}

// round 7
// speedup vs baseline: 1.4840x; 1.4840x over previous
#include <cuda_runtime.h>
#include <cuda_bf16.h>
#include <cstdint>
#include <math.h>

// Problem constants
#define B_    4
#define SQ_   1024
#define SKV_  4096
#define DQ_   1024
#define DKV_  768
#define H_    16
#define DH_   64
#define DOUT_ 256

#define SWZ(o) ((o) ^ (((o) >> 3) & 0x70))

// ---------------------------------------------------------------------------
// Scratch (static device globals; bf16 buffers 16B aligned for cp.async)
// ---------------------------------------------------------------------------
#define AL16 __align__(16)
// raw-input splits
__device__ AL16 __nv_bfloat16 g_sqh[(size_t)B_ * SQ_  * DQ_ ], g_sql[(size_t)B_ * SQ_  * DQ_ ];
__device__ AL16 __nv_bfloat16 g_skh[(size_t)B_ * SKV_ * DKV_], g_skl[(size_t)B_ * SKV_ * DKV_];
__device__ AL16 __nv_bfloat16 g_svh[(size_t)B_ * SKV_ * DKV_], g_svl[(size_t)B_ * SKV_ * DKV_];
// weight splits
__device__ AL16 __nv_bfloat16 g_wqh[DQ_ * DQ_ ],  g_wql[DQ_ * DQ_ ];
__device__ AL16 __nv_bfloat16 g_wkh[DQ_ * DKV_],  g_wkl[DQ_ * DKV_];
__device__ AL16 __nv_bfloat16 g_wvh[DQ_ * DKV_],  g_wvl[DQ_ * DKV_];
__device__ AL16 __nv_bfloat16 g_woh[DOUT_ * DQ_], g_wol[DOUT_ * DQ_];
// projected tensors (bf16 hi/lo)
__device__ AL16 __nv_bfloat16 g_qh [(size_t)B_ * SQ_  * DQ_], g_ql [(size_t)B_ * SQ_  * DQ_];
__device__ AL16 __nv_bfloat16 g_kh [(size_t)B_ * SKV_ * DQ_], g_kl [(size_t)B_ * SKV_ * DQ_];
__device__ AL16 __nv_bfloat16 g_vh [(size_t)B_ * SKV_ * DQ_], g_vl [(size_t)B_ * SKV_ * DQ_];
__device__ AL16 __nv_bfloat16 g_vth[(size_t)B_ * DQ_ * SKV_], g_vtl[(size_t)B_ * DQ_ * SKV_];
// attention output pre-Wo (bf16 hi/lo)
__device__ AL16 __nv_bfloat16 g_ath[(size_t)B_ * SQ_ * DQ_], g_atl[(size_t)B_ * SQ_ * DQ_];
// transposed mask u8 [b][q][kv]
__device__ AL16 unsigned char g_maskT[(size_t)B_ * SQ_ * SKV_];
__device__ int g_mask_flag;

// ---------------------------------------------------------------------------
// Mask dtype probe
// ---------------------------------------------------------------------------
__global__ void probe_mask_kernel(const unsigned int* __restrict__ m)
{
    if (blockIdx.x != 0 || threadIdx.x != 0) return;
    int is_i32 = 1, is_f32 = 1;
    for (int i = 0; i < 4096; i++) {
        unsigned v = m[i];
        if (v > 1u) is_i32 = 0;
        if (v != 0u && v != 0x3F800000u) is_f32 = 0;
    }
    g_mask_flag = is_i32 ? 1 : (is_f32 ? 2 : 0);
}

__device__ __forceinline__ bool read_mask(const void* m, long i, int flag)
{
    if (flag == 1) return ((const int*)m)[i] != 0;
    if (flag == 2) return ((const float*)m)[i] != 0.0f;
    return ((const unsigned char*)m)[i] != 0;
}

// ---------------------------------------------------------------------------
// Mask transpose: mask[b][kv][q] (any dtype) -> u8 maskT[b][q][kv]
// ---------------------------------------------------------------------------
__global__ __launch_bounds__(256)
void transpose_mask_kernel(const void* __restrict__ mask,
                           unsigned char* __restrict__ maskT)
{
    __shared__ unsigned char t[32][33];
    const int b   = blockIdx.z;
    const int kv0 = blockIdx.x * 32, q0 = blockIdx.y * 32;
    const int x = threadIdx.x, y = threadIdx.y;      // 32 x 8
    const int flag = g_mask_flag;
#pragma unroll
    for (int i = y; i < 32; i += 8)
        t[i][x] = read_mask(mask, ((long)b * SKV_ + kv0 + i) * SQ_ + q0 + x, flag) ? 1 : 0;
    __syncthreads();
#pragma unroll
    for (int i = y; i < 32; i += 8)
        maskT[((long)b * SQ_ + q0 + i) * SKV_ + kv0 + x] = t[x][i];
}

// ---------------------------------------------------------------------------
// Primitives
// ---------------------------------------------------------------------------
__device__ __forceinline__ uint32_t smem_to_u32(const void* p) {
    uint32_t a;
    asm("{ .reg .u64 t; cvta.to.shared.u64 t, %1; cvt.u32.u64 %0, t; }"
        : "=r"(a) : "l"(p));
    return a;
}

__device__ __forceinline__ void ldm_x4(uint32_t addr, uint32_t* r) {
    asm volatile("ldmatrix.sync.aligned.m8n8.x4.shared.b16 {%0,%1,%2,%3}, [%4];"
                 : "=r"(r[0]), "=r"(r[1]), "=r"(r[2]), "=r"(r[3]) : "r"(addr));
}

__device__ __forceinline__ void mma_bf16(float* d, const uint32_t* a,
                                         uint32_t b0, uint32_t b1) {
    asm volatile(
        "mma.sync.aligned.m16n8k16.row.col.f32.bf16.bf16.f32 "
        "{%0,%1,%2,%3}, {%4,%5,%6,%7}, {%8,%9}, {%0,%1,%2,%3};"
        : "+f"(d[0]), "+f"(d[1]), "+f"(d[2]), "+f"(d[3])
        : "r"(a[0]), "r"(a[1]), "r"(a[2]), "r"(a[3]), "r"(b0), "r"(b1));
}

__device__ __forceinline__ uint32_t pk2(__nv_bfloat16 a, __nv_bfloat16 b)
{
    return (uint32_t)__bfloat16_as_ushort(a) | ((uint32_t)__bfloat16_as_ushort(b) << 16);
}

__device__ __forceinline__ void cvt1(float4 v, char* hb, char* lb, int r, int cg)
{
    __nv_bfloat16 h0 = __float2bfloat16(v.x);
    __nv_bfloat16 h1 = __float2bfloat16(v.y);
    __nv_bfloat16 h2 = __float2bfloat16(v.z);
    __nv_bfloat16 h3 = __float2bfloat16(v.w);
    __nv_bfloat16 l0 = __float2bfloat16(v.x - __bfloat162float(h0));
    __nv_bfloat16 l1 = __float2bfloat16(v.y - __bfloat162float(h1));
    __nv_bfloat16 l2 = __float2bfloat16(v.z - __bfloat162float(h2));
    __nv_bfloat16 l3 = __float2bfloat16(v.w - __bfloat162float(h3));
    unsigned off = SWZ((unsigned)(r * 128 + (cg << 1)));
    *(uint2*)(hb + off) = make_uint2(pk2(h0, h1), pk2(h2, h3));
    *(uint2*)(lb + off) = make_uint2(pk2(l0, l1), pk2(l2, l3));
}

// cp.async a ROWSx64-bf16 tile (rows of 128B) into SW128 swizzled smem
template<int ROWS>
__device__ __forceinline__ void cpa_tile(uint32_t dst, const __nv_bfloat16* src,
                                         int ld, int tid)
{
#pragma unroll
    for (int i = 0; i < ROWS / 32; i++) {
        int f = tid + i * 256;
        int r = f >> 3, c = f & 7;
        uint32_t d = dst + SWZ((unsigned)(r * 128 + c * 16));
        const void* s = src + (long)r * ld + c * 8;
        asm volatile("cp.async.cg.shared.global [%0], [%1], 16;" :: "r"(d), "l"(s));
    }
}

// ---------------------------------------------------------------------------
// fp32 -> bf16 hi/lo split (elementwise, n divisible by 1024)
// ---------------------------------------------------------------------------
__global__ __launch_bounds__(256)
void split_kernel(const float* __restrict__ src,
                  __nv_bfloat16* __restrict__ h, __nv_bfloat16* __restrict__ l)
{
    long i = ((long)blockIdx.x * 256 + threadIdx.x) * 4;
    float4 v = *(const float4*)(src + i);
    __nv_bfloat16 h0 = __float2bfloat16(v.x), h1 = __float2bfloat16(v.y);
    __nv_bfloat16 h2 = __float2bfloat16(v.z), h3 = __float2bfloat16(v.w);
    *(uint2*)(h + i) = make_uint2(pk2(h0, h1), pk2(h2, h3));
    *(uint2*)(l + i) = make_uint2(
        pk2(__float2bfloat16(v.x - __bfloat162float(h0)),
            __float2bfloat16(v.y - __bfloat162float(h1))),
        pk2(__float2bfloat16(v.z - __bfloat162float(h2)),
            __float2bfloat16(v.w - __bfloat162float(h3))));
}

// ---------------------------------------------------------------------------
// bf16 hi/lo GEMM via HMMA.  D[128, NT] per CTA = A[128,K] @ B[NT,K]^T
// MODE 0: projections: bf16 A/B, +bias, write bf16 h/l
// MODE 1: scores per z=(b,h): bf16 q/k, write fp32 * 0.125 (no mask)
// MODE 2: PV per z=(b,h): A = fp32 Wt (inline split), B = vt h/l, write bf16 h/l
// MODE 3: Wo: bf16 A/B, +bias, write fp32
// ---------------------------------------------------------------------------
template<int NT, int MODE>
__global__ void __launch_bounds__(256, 1)
hgemm_kernel(const __nv_bfloat16* __restrict__ Ah, const __nv_bfloat16* __restrict__ Al,
             const float* __restrict__ Af, int lda,
             const __nv_bfloat16* __restrict__ Bh, const __nv_bfloat16* __restrict__ Bl, int ldb,
             const float* __restrict__ bias,
             void* __restrict__ C0, void* __restrict__ C1, int ldc, int Kdim)
{
    extern __shared__ char smem[];
    constexpr int NF = NT / 16;
    constexpr unsigned ABY = 128 * 128;
    constexpr unsigned BBY = NT * 128;
    constexpr unsigned BUFSZ = 2 * ABY + 2 * BBY;

    const uint32_t sbase = smem_to_u32(smem);
    const int tid = threadIdx.x;
    const int wid = tid >> 5, lid = tid & 31;
    const int wm = wid & 3, wn = wid >> 2;           // 4(m) x 2(n)
    const int m0 = blockIdx.y * 128, n0 = blockIdx.x * NT, z = blockIdx.z;

    const __nv_bfloat16 *Aph = nullptr, *Apl = nullptr, *Bph, *Bpl;
    const float* Afp = nullptr;
    int LDA, LDB, LDC;
    char *Cp0, *Cp1 = nullptr;
    if (MODE == 0 || MODE == 3) {
        Aph = Ah + (long)m0 * lda;  Apl = Al + (long)m0 * lda;  LDA = lda;
        Bph = Bh + (long)n0 * ldb;  Bpl = Bl + (long)n0 * ldb;  LDB = ldb;
        LDC = ldc;
        long co = (long)m0 * ldc + n0;
        if (MODE == 0) { Cp0 = (char*)((__nv_bfloat16*)C0 + co); Cp1 = (char*)((__nv_bfloat16*)C1 + co); }
        else           { Cp0 = (char*)((float*)C0 + co); }
    } else if (MODE == 1) {
        int b = z >> 4, h = z & 15;
        long ao = ((long)b * SQ_  + m0) * DQ_ + h * DH_;
        long bo = ((long)b * SKV_ + n0) * DQ_ + h * DH_;
        Aph = Ah + ao; Apl = Al + ao; LDA = DQ_;
        Bph = Bh + bo; Bpl = Bl + bo; LDB = DQ_;
        LDC = SKV_;
        Cp0 = (char*)((float*)C0 + ((long)z * SQ_ + m0) * SKV_ + n0);
    } else {
        int b = z >> 4, h = z & 15;
        Afp = Af + ((long)z * SQ_ + m0) * SKV_;          LDA = SKV_;
        long bo = ((long)(b * DQ_ + h * DH_)) * SKV_;
        Bph = Bh + bo; Bpl = Bl + bo;                    LDB = SKV_;
        LDC = DQ_;
        long co = ((long)b * SQ_ + m0) * DQ_ + h * DH_;
        Cp0 = (char*)((__nv_bfloat16*)C0 + co); Cp1 = (char*)((__nv_bfloat16*)C1 + co);
    }

    float dc[2 * NF][4];
#pragma unroll
    for (int i = 0; i < 2 * NF; i++)
#pragma unroll
        for (int j = 0; j < 4; j++) dc[i][j] = 0.0f;

    float4 stg[MODE == 2 ? 8 : 1];

    const int ns = Kdim >> 6;

    auto issueB = [&](int s) {
        uint32_t base = sbase + (unsigned)(s & 1) * BUFSZ;
        cpa_tile<NT>(base + 2 * ABY,       Bph + (long)s * 64, LDB, tid);
        cpa_tile<NT>(base + 2 * ABY + BBY, Bpl + (long)s * 64, LDB, tid);
    };
    auto issueA = [&](int s) {
        uint32_t base = sbase + (unsigned)(s & 1) * BUFSZ;
        cpa_tile<128>(base,       Aph + (long)s * 64, LDA, tid);
        cpa_tile<128>(base + ABY, Apl + (long)s * 64, LDA, tid);
    };
    auto ldgA = [&](int s) {       // MODE 2: fp32 weights -> regs
        const float* As = Afp + s * 64;
#pragma unroll
        for (int i = 0; i < 8; i++) {
            int f = tid + i * 256, r = f >> 4, cg = (f & 15) << 2;
            stg[i] = *(const float4*)(As + (long)r * LDA + cg);
        }
    };
    auto cvtstsA = [&](int s) {    // MODE 2: regs -> bf16 h/l smem
        char* ah = smem + (size_t)(s & 1) * BUFSZ;
        char* al = ah + ABY;
#pragma unroll
        for (int i = 0; i < 8; i++) {
            int f = tid + i * 256;
            cvt1(stg[i], ah, al, f >> 4, (f & 15) << 2);
        }
    };

    auto compute = [&](int buf) {
        const uint32_t sA  = sbase + (unsigned)buf * BUFSZ;
        const uint32_t sAl = sA + ABY;
        const uint32_t sB  = sA + 2 * ABY;
        const uint32_t sBl = sB + BBY;
        const int lr = lid & 15, hsel = (lid >> 4) << 4;
#pragma unroll
        for (int ks = 0; ks < 4; ks++) {
            const int kb = ks * 32 + hsel;
            uint32_t aH[2][4], aL[2][4];
#pragma unroll
            for (int i = 0; i < 2; i++) {
                unsigned off = SWZ((unsigned)((wm * 32 + i * 16 + lr) * 128 + kb));
                ldm_x4(sA + off, aH[i]);
                ldm_x4(sAl + off, aL[i]);
            }
#pragma unroll
            for (int jj = 0; jj < NF / 2; jj++) {
                unsigned off = SWZ((unsigned)((wn * (NT / 2) + jj * 16 + lr) * 128 + kb));
                uint32_t bH[4], bL[4];
                ldm_x4(sB + off, bH);
                ldm_x4(sBl + off, bL);
#pragma unroll
                for (int i = 0; i < 2; i++) {
#pragma unroll
                    for (int t = 0; t < 2; t++) {
                        float* d = dc[i * NF + jj * 2 + t];
                        mma_bf16(d, aH[i], bH[t], bH[t + 2]);
                        mma_bf16(d, aH[i], bL[t], bL[t + 2]);
                        mma_bf16(d, aL[i], bH[t], bH[t + 2]);
                    }
                }
            }
        }
    };

    if (MODE == 2) {
        ldgA(0);
        issueB(0);
        asm volatile("cp.async.commit_group;" ::: "memory");
        cvtstsA(0);
        for (int s = 0; s < ns; s++) {
            if (s + 1 < ns) {
                ldgA(s + 1);
                issueB(s + 1);
                asm volatile("cp.async.commit_group;" ::: "memory");
                asm volatile("cp.async.wait_group 1;" ::: "memory");
            } else {
                asm volatile("cp.async.wait_group 0;" ::: "memory");
            }
            __syncthreads();
            compute(s & 1);
            if (s + 1 < ns) cvtstsA(s + 1);
            __syncthreads();
        }
    } else {
        issueA(0); issueB(0);
        asm volatile("cp.async.commit_group;" ::: "memory");
        for (int s = 0; s < ns; s++) {
            if (s + 1 < ns) {
                issueA(s + 1); issueB(s + 1);
                asm volatile("cp.async.commit_group;" ::: "memory");
                asm volatile("cp.async.wait_group 1;" ::: "memory");
            } else {
                asm volatile("cp.async.wait_group 0;" ::: "memory");
            }
            __syncthreads();
            compute(s & 1);
            __syncthreads();
        }
    }

    // ---- epilogue ----
#pragma unroll
    for (int i = 0; i < 2; i++) {
#pragma unroll
        for (int f = 0; f < NF; f++) {
            const float* d = dc[i * NF + f];
            int rl = wm * 32 + i * 16 + (lid >> 2);
            int cl = wn * (NT / 2) + f * 8 + ((lid & 3) << 1);
            if (MODE == 0 || MODE == 2) {
                float bx = 0.0f, by = 0.0f;
                if (MODE == 0) { float2 bb = *(const float2*)(bias + n0 + cl); bx = bb.x; by = bb.y; }
                float v0 = d[0] + bx, v1 = d[1] + by;
                float v2 = d[2] + bx, v3 = d[3] + by;
                __nv_bfloat16 h0 = __float2bfloat16(v0), h1 = __float2bfloat16(v1);
                __nv_bfloat16 h2 = __float2bfloat16(v2), h3 = __float2bfloat16(v3);
                __nv_bfloat16* ch = (__nv_bfloat16*)Cp0;
                __nv_bfloat16* cll = (__nv_bfloat16*)Cp1;
                *(uint32_t*)(ch + (long)rl * LDC + cl)       = pk2(h0, h1);
                *(uint32_t*)(ch + (long)(rl + 8) * LDC + cl) = pk2(h2, h3);
                *(uint32_t*)(cll + (long)rl * LDC + cl) =
                    pk2(__float2bfloat16(v0 - __bfloat162float(h0)),
                        __float2bfloat16(v1 - __bfloat162float(h1)));
                *(uint32_t*)(cll + (long)(rl + 8) * LDC + cl) =
                    pk2(__float2bfloat16(v2 - __bfloat162float(h2)),
                        __float2bfloat16(v3 - __bfloat162float(h3)));
            } else if (MODE == 1) {
                float* cp = (float*)Cp0;
                *(float2*)(cp + (long)rl * LDC + cl) =
                    make_float2(d[0] * 0.125f, d[1] * 0.125f);
                *(float2*)(cp + (long)(rl + 8) * LDC + cl) =
                    make_float2(d[2] * 0.125f, d[3] * 0.125f);
            } else {
                float2 bb = *(const float2*)(bias + n0 + cl);
                float* cp = (float*)Cp0;
                *(float2*)(cp + (long)rl * LDC + cl) =
                    make_float2(d[0] + bb.x, d[1] + bb.y);
                *(float2*)(cp + (long)(rl + 8) * LDC + cl) =
                    make_float2(d[2] + bb.x, d[3] + bb.y);
            }
        }
    }
}

// ---------------------------------------------------------------------------
// bf16 transpose: v h/l [b][kv][ch] -> vt h/l [b][ch][kv]
// ---------------------------------------------------------------------------
__global__ __launch_bounds__(256)
void transpose_bf16_kernel(const __nv_bfloat16* __restrict__ vh,
                           const __nv_bfloat16* __restrict__ vl,
                           __nv_bfloat16* __restrict__ vth,
                           __nv_bfloat16* __restrict__ vtl)
{
    __shared__ __nv_bfloat16 th[32][34], tl[32][34];
    const int b   = blockIdx.z;
    const int kv0 = blockIdx.x * 32, ch0 = blockIdx.y * 32;
    const int x = threadIdx.x, y = threadIdx.y;      // 32 x 8
#pragma unroll
    for (int i = y; i < 32; i += 8) {
        long src = ((long)b * SKV_ + kv0 + i) * DQ_ + ch0 + x;
        th[i][x] = vh[src];
        tl[i][x] = vl[src];
    }
    __syncthreads();
#pragma unroll
    for (int i = y; i < 32; i += 8) {
        long dst = ((long)b * DQ_ + ch0 + i) * SKV_ + kv0 + x;
        vth[dst] = th[x][i];
        vtl[dst] = tl[x][i];
    }
}

// ---------------------------------------------------------------------------
// Row softmax over SKV=4096 in place; applies mask (from u8 maskT) before max
// ---------------------------------------------------------------------------
__global__ __launch_bounds__(256)
void softmax_kernel(float* __restrict__ Wt, const unsigned char* __restrict__ maskT)
{
    __shared__ float shm[8];
    __shared__ float shs[8];
    __shared__ float bmx, bsum;

    const long row = blockIdx.x;                 // [b][h][q]
    const int b = (int)(row >> 14);              // / (H*SQ)
    const int q = (int)(row & (SQ_ - 1));
    float* p = Wt + row * SKV_;
    const unsigned char* mrow = maskT + ((long)b * SQ_ + q) * SKV_;

    const int tid  = threadIdx.x;
    const int lane = tid & 31;
    const int wrp  = tid >> 5;

    float s[16];
    float mx = -3.4e38f;
#pragma unroll
    for (int i = 0; i < 16; i++) {
        int idx = tid + (i << 8);
        float v = p[idx];
        if (mrow[idx]) v = -1.0e9f;
        s[i] = v;
        mx = fmaxf(mx, v);
    }
#pragma unroll
    for (int o = 16; o; o >>= 1) mx = fmaxf(mx, __shfl_xor_sync(0xFFFFFFFFu, mx, o));
    if (lane == 0) shm[wrp] = mx;
    __syncthreads();
    if (tid == 0) {
        float v = shm[0];
#pragma unroll
        for (int i = 1; i < 8; i++) v = fmaxf(v, shm[i]);
        bmx = v;
    }
    __syncthreads();
    mx = bmx;

    float sum = 0.0f;
#pragma unroll
    for (int i = 0; i < 16; i++) {
        s[i] = __expf(s[i] - mx);
        sum += s[i];
    }
#pragma unroll
    for (int o = 16; o; o >>= 1) sum += __shfl_xor_sync(0xFFFFFFFFu, sum, o);
    if (lane == 0) shs[wrp] = sum;
    __syncthreads();
    if (tid == 0) {
        float v = shs[0];
#pragma unroll
        for (int i = 1; i < 8; i++) v += shs[i];
        bsum = v;
    }
    __syncthreads();
    const float inv = 1.0f / bsum;

#pragma unroll
    for (int i = 0; i < 16; i++) p[tid + (i << 8)] = s[i] * inv;
}

// ---------------------------------------------------------------------------
// Launch
// ---------------------------------------------------------------------------
extern "C" void kernel_launch(void* const* d_in, const int* in_sizes, int n_in,
                              void* d_out, int out_size)
{
    (void)in_sizes; (void)n_in; (void)out_size;

    const float* Q   = (const float*)d_in[0];
    const float* K   = (const float*)d_in[1];
    const float* V   = (const float*)d_in[2];
    const void*  Msk = d_in[3];
    const float* bq  = (const float*)d_in[5];
    const float* Wq  = (const float*)d_in[4];
    const float* Wk  = (const float*)d_in[6];
    const float* bk  = (const float*)d_in[7];
    const float* Wv  = (const float*)d_in[8];
    const float* bv  = (const float*)d_in[9];
    const float* Wo  = (const float*)d_in[10];
    const float* bo  = (const float*)d_in[11];

    float* out = (float*)d_out;                       // [B,SQ,DOUT]
    float* Wt  = out + (size_t)B_ * SQ_ * DOUT_;      // [B,H,SQ,SKV]

    __nv_bfloat16 *sqh, *sql, *skh, *skl, *svh, *svl;
    __nv_bfloat16 *wqh, *wql, *wkh, *wkl, *wvh, *wvl, *woh, *wol;
    __nv_bfloat16 *qh, *ql, *kh, *kl, *vh, *vl, *vth, *vtl, *ath, *atl;
    unsigned char* mT;
    cudaGetSymbolAddress((void**)&sqh, g_sqh); cudaGetSymbolAddress((void**)&sql, g_sql);
    cudaGetSymbolAddress((void**)&skh, g_skh); cudaGetSymbolAddress((void**)&skl, g_skl);
    cudaGetSymbolAddress((void**)&svh, g_svh); cudaGetSymbolAddress((void**)&svl, g_svl);
    cudaGetSymbolAddress((void**)&wqh, g_wqh); cudaGetSymbolAddress((void**)&wql, g_wql);
    cudaGetSymbolAddress((void**)&wkh, g_wkh); cudaGetSymbolAddress((void**)&wkl, g_wkl);
    cudaGetSymbolAddress((void**)&wvh, g_wvh); cudaGetSymbolAddress((void**)&wvl, g_wvl);
    cudaGetSymbolAddress((void**)&woh, g_woh); cudaGetSymbolAddress((void**)&wol, g_wol);
    cudaGetSymbolAddress((void**)&qh,  g_qh);  cudaGetSymbolAddress((void**)&ql,  g_ql);
    cudaGetSymbolAddress((void**)&kh,  g_kh);  cudaGetSymbolAddress((void**)&kl,  g_kl);
    cudaGetSymbolAddress((void**)&vh,  g_vh);  cudaGetSymbolAddress((void**)&vl,  g_vl);
    cudaGetSymbolAddress((void**)&vth, g_vth); cudaGetSymbolAddress((void**)&vtl, g_vtl);
    cudaGetSymbolAddress((void**)&ath, g_ath); cudaGetSymbolAddress((void**)&atl, g_atl);
    cudaGetSymbolAddress((void**)&mT,  g_maskT);

    // smem: 128-tile buf = 64KB, 64-tile buf = 48KB
    const int SM0 = 2 * 65536;        // 131072: modes 0 (2-stage, NT128)
    const int SM1 = 65536;            //  65536: mode 1 (1-stage, NT128, K=64)
    const int SM2 = 2 * 49152;        //  98304: modes 2,3 (2-stage, NT64)
    cudaFuncSetAttribute(hgemm_kernel<128, 0>, cudaFuncAttributeMaxDynamicSharedMemorySize, SM0);
    cudaFuncSetAttribute(hgemm_kernel<128, 1>, cudaFuncAttributeMaxDynamicSharedMemorySize, SM1);
    cudaFuncSetAttribute(hgemm_kernel<64, 2>,  cudaFuncAttributeMaxDynamicSharedMemorySize, SM2);
    cudaFuncSetAttribute(hgemm_kernel<64, 3>,  cudaFuncAttributeMaxDynamicSharedMemorySize, SM2);

    // 0) probe + operand splits + mask transpose
    probe_mask_kernel<<<1, 1>>>((const unsigned int*)Msk);
    split_kernel<<<(B_ * SQ_ * DQ_)   / 1024, 256>>>(Q,  sqh, sql);
    split_kernel<<<(B_ * SKV_ * DKV_) / 1024, 256>>>(K, skh, skl);
    split_kernel<<<(B_ * SKV_ * DKV_) / 1024, 256>>>(V, svh, svl);
    split_kernel<<<(DQ_ * DQ_)   / 1024, 256>>>(Wq, wqh, wql);
    split_kernel<<<(DQ_ * DKV_)  / 1024, 256>>>(Wk, wkh, wkl);
    split_kernel<<<(DQ_ * DKV_)  / 1024, 256>>>(Wv, wvh, wvl);
    split_kernel<<<(DOUT_ * DQ_) / 1024, 256>>>(Wo, woh, wol);
    transpose_mask_kernel<<<dim3(SKV_ / 32, SQ_ / 32, B_), dim3(32, 8)>>>(Msk, mT);

    // 1) projections -> bf16 h/l
    hgemm_kernel<128, 0><<<dim3(DQ_ / 128, (B_ * SQ_) / 128, 1), 256, SM0>>>(
        sqh, sql, nullptr, DQ_, wqh, wql, DQ_, bq, qh, ql, DQ_, DQ_);
    hgemm_kernel<128, 0><<<dim3(DQ_ / 128, (B_ * SKV_) / 128, 1), 256, SM0>>>(
        skh, skl, nullptr, DKV_, wkh, wkl, DKV_, bk, kh, kl, DQ_, DKV_);
    hgemm_kernel<128, 0><<<dim3(DQ_ / 128, (B_ * SKV_) / 128, 1), 256, SM0>>>(
        svh, svl, nullptr, DKV_, wvh, wvl, DKV_, bv, vh, vl, DQ_, DKV_);

    // 1b) transpose projected V (bf16 h/l)
    transpose_bf16_kernel<<<dim3(SKV_ / 32, DQ_ / 32, B_), dim3(32, 8)>>>(
        vh, vl, vth, vtl);

    // 2) raw scores * 0.125 -> fp32 weights region of d_out (mask in softmax)
    hgemm_kernel<128, 1><<<dim3(SKV_ / 128, SQ_ / 128, B_ * H_), 256, SM1>>>(
        qh, ql, nullptr, 0, kh, kl, 0, nullptr, Wt, nullptr, 0, DH_);

    // 3) masked softmax in place
    softmax_kernel<<<B_ * H_ * SQ_, 256>>>(Wt, mT);

    // 4) PV: A = fp32 weights (inline split), B = vt bf16 h/l -> att bf16 h/l
    hgemm_kernel<64, 2><<<dim3(1, SQ_ / 128, B_ * H_), 256, SM2>>>(
        nullptr, nullptr, Wt, 0, vth, vtl, 0, nullptr, ath, atl, 0, SKV_);

    // 5) output projection -> fp32 front of d_out
    hgemm_kernel<64, 3><<<dim3(DOUT_ / 64, (B_ * SQ_) / 128, 1), 256, SM2>>>(
        ath, atl, nullptr, DQ_, woh, wol, DQ_, bo, out, nullptr, DOUT_, DQ_);
}

// round 9
// speedup vs baseline: 1.4974x; 1.0090x over previous
#include <cuda_runtime.h>
#include <cuda_bf16.h>
#include <cstdint>
#include <math.h>

// Problem constants
#define B_    4
#define SQ_   1024
#define SKV_  4096
#define DQ_   1024
#define DKV_  768
#define H_    16
#define DH_   64
#define DOUT_ 256

#define SWZ(o) ((o) ^ (((o) >> 3) & 0x70))

// ---------------------------------------------------------------------------
// Scratch (static device globals; bf16 buffers 16B aligned for cp.async)
// ---------------------------------------------------------------------------
#define AL16 __align__(16)
// raw-input splits
__device__ AL16 __nv_bfloat16 g_sqh[(size_t)B_ * SQ_  * DQ_ ], g_sql[(size_t)B_ * SQ_  * DQ_ ];
__device__ AL16 __nv_bfloat16 g_skh[(size_t)B_ * SKV_ * DKV_], g_skl[(size_t)B_ * SKV_ * DKV_];
__device__ AL16 __nv_bfloat16 g_svh[(size_t)B_ * SKV_ * DKV_], g_svl[(size_t)B_ * SKV_ * DKV_];
// weight splits
__device__ AL16 __nv_bfloat16 g_wqh[DQ_ * DQ_ ],  g_wql[DQ_ * DQ_ ];
__device__ AL16 __nv_bfloat16 g_wkh[DQ_ * DKV_],  g_wkl[DQ_ * DKV_];
__device__ AL16 __nv_bfloat16 g_wvh[DQ_ * DKV_],  g_wvl[DQ_ * DKV_];
__device__ AL16 __nv_bfloat16 g_woh[DOUT_ * DQ_], g_wol[DOUT_ * DQ_];
// projected tensors (bf16 hi/lo)
__device__ AL16 __nv_bfloat16 g_qh [(size_t)B_ * SQ_  * DQ_], g_ql [(size_t)B_ * SQ_  * DQ_];
__device__ AL16 __nv_bfloat16 g_kh [(size_t)B_ * SKV_ * DQ_], g_kl [(size_t)B_ * SKV_ * DQ_];
__device__ AL16 __nv_bfloat16 g_vh [(size_t)B_ * SKV_ * DQ_], g_vl [(size_t)B_ * SKV_ * DQ_];
__device__ AL16 __nv_bfloat16 g_vth[(size_t)B_ * DQ_ * SKV_], g_vtl[(size_t)B_ * DQ_ * SKV_];
// attention output pre-Wo (bf16 hi/lo)
__device__ AL16 __nv_bfloat16 g_ath[(size_t)B_ * SQ_ * DQ_], g_atl[(size_t)B_ * SQ_ * DQ_];
// transposed mask u8 [b][q][kv]
__device__ AL16 unsigned char g_maskT[(size_t)B_ * SQ_ * SKV_];
// softmax stats: per (row, kv-tile) and per row
#define NROWS_ (B_ * H_ * SQ_)
#define NTILES_ (SKV_ / 128)
__device__ AL16 float g_gmax[(size_t)NROWS_ * NTILES_];
__device__ AL16 float g_gsum[(size_t)NROWS_ * NTILES_];
__device__ AL16 float g_rowM[NROWS_];
__device__ AL16 float g_rowI[NROWS_];
__device__ int g_mask_flag;

// ---------------------------------------------------------------------------
// Mask dtype probe
// ---------------------------------------------------------------------------
__global__ void probe_mask_kernel(const unsigned int* __restrict__ m)
{
    if (blockIdx.x != 0 || threadIdx.x != 0) return;
    int is_i32 = 1, is_f32 = 1;
    for (int i = 0; i < 4096; i++) {
        unsigned v = m[i];
        if (v > 1u) is_i32 = 0;
        if (v != 0u && v != 0x3F800000u) is_f32 = 0;
    }
    g_mask_flag = is_i32 ? 1 : (is_f32 ? 2 : 0);
}

__device__ __forceinline__ bool read_mask(const void* m, long i, int flag)
{
    if (flag == 1) return ((const int*)m)[i] != 0;
    if (flag == 2) return ((const float*)m)[i] != 0.0f;
    return ((const unsigned char*)m)[i] != 0;
}

// ---------------------------------------------------------------------------
// Mask transpose: mask[b][kv][q] (any dtype) -> u8 maskT[b][q][kv]
// ---------------------------------------------------------------------------
__global__ __launch_bounds__(256)
void transpose_mask_kernel(const void* __restrict__ mask,
                           unsigned char* __restrict__ maskT)
{
    __shared__ unsigned char t[32][33];
    const int b   = blockIdx.z;
    const int kv0 = blockIdx.x * 32, q0 = blockIdx.y * 32;
    const int x = threadIdx.x, y = threadIdx.y;      // 32 x 8
    const int flag = g_mask_flag;
#pragma unroll
    for (int i = y; i < 32; i += 8)
        t[i][x] = read_mask(mask, ((long)b * SKV_ + kv0 + i) * SQ_ + q0 + x, flag) ? 1 : 0;
    __syncthreads();
#pragma unroll
    for (int i = y; i < 32; i += 8)
        maskT[((long)b * SQ_ + q0 + i) * SKV_ + kv0 + x] = t[x][i];
}

// ---------------------------------------------------------------------------
// Primitives
// ---------------------------------------------------------------------------
__device__ __forceinline__ uint32_t smem_to_u32(const void* p) {
    uint32_t a;
    asm("{ .reg .u64 t; cvta.to.shared.u64 t, %1; cvt.u32.u64 %0, t; }"
        : "=r"(a) : "l"(p));
    return a;
}

__device__ __forceinline__ void ldm_x4(uint32_t addr, uint32_t* r) {
    asm volatile("ldmatrix.sync.aligned.m8n8.x4.shared.b16 {%0,%1,%2,%3}, [%4];"
                 : "=r"(r[0]), "=r"(r[1]), "=r"(r[2]), "=r"(r[3]) : "r"(addr));
}

__device__ __forceinline__ void mma_bf16(float* d, const uint32_t* a,
                                         uint32_t b0, uint32_t b1) {
    asm volatile(
        "mma.sync.aligned.m16n8k16.row.col.f32.bf16.bf16.f32 "
        "{%0,%1,%2,%3}, {%4,%5,%6,%7}, {%8,%9}, {%0,%1,%2,%3};"
        : "+f"(d[0]), "+f"(d[1]), "+f"(d[2]), "+f"(d[3])
        : "r"(a[0]), "r"(a[1]), "r"(a[2]), "r"(a[3]), "r"(b0), "r"(b1));
}

__device__ __forceinline__ uint32_t pk2(__nv_bfloat16 a, __nv_bfloat16 b)
{
    return (uint32_t)__bfloat16_as_ushort(a) | ((uint32_t)__bfloat16_as_ushort(b) << 16);
}

__device__ __forceinline__ void cvt1(float4 v, char* hb, char* lb, int r, int cg)
{
    __nv_bfloat16 h0 = __float2bfloat16(v.x);
    __nv_bfloat16 h1 = __float2bfloat16(v.y);
    __nv_bfloat16 h2 = __float2bfloat16(v.z);
    __nv_bfloat16 h3 = __float2bfloat16(v.w);
    __nv_bfloat16 l0 = __float2bfloat16(v.x - __bfloat162float(h0));
    __nv_bfloat16 l1 = __float2bfloat16(v.y - __bfloat162float(h1));
    __nv_bfloat16 l2 = __float2bfloat16(v.z - __bfloat162float(h2));
    __nv_bfloat16 l3 = __float2bfloat16(v.w - __bfloat162float(h3));
    unsigned off = SWZ((unsigned)(r * 128 + (cg << 1)));
    *(uint2*)(hb + off) = make_uint2(pk2(h0, h1), pk2(h2, h3));
    *(uint2*)(lb + off) = make_uint2(pk2(l0, l1), pk2(l2, l3));
}

// cp.async a ROWSx64-bf16 tile (rows of 128B) into SW128 swizzled smem
template<int ROWS>
__device__ __forceinline__ void cpa_tile(uint32_t dst, const __nv_bfloat16* src,
                                         int ld, int tid)
{
#pragma unroll
    for (int i = 0; i < ROWS / 32; i++) {
        int f = tid + i * 256;
        int r = f >> 3, c = f & 7;
        uint32_t d = dst + SWZ((unsigned)(r * 128 + c * 16));
        const void* s = src + (long)r * ld + c * 8;
        asm volatile("cp.async.cg.shared.global [%0], [%1], 16;" :: "r"(d), "l"(s));
    }
}

// ---------------------------------------------------------------------------
// fp32 -> bf16 hi/lo split (elementwise, n divisible by 1024)
// ---------------------------------------------------------------------------
__global__ __launch_bounds__(256)
void split_kernel(const float* __restrict__ src,
                  __nv_bfloat16* __restrict__ h, __nv_bfloat16* __restrict__ l)
{
    long i = ((long)blockIdx.x * 256 + threadIdx.x) * 4;
    float4 v = *(const float4*)(src + i);
    __nv_bfloat16 h0 = __float2bfloat16(v.x), h1 = __float2bfloat16(v.y);
    __nv_bfloat16 h2 = __float2bfloat16(v.z), h3 = __float2bfloat16(v.w);
    *(uint2*)(h + i) = make_uint2(pk2(h0, h1), pk2(h2, h3));
    *(uint2*)(l + i) = make_uint2(
        pk2(__float2bfloat16(v.x - __bfloat162float(h0)),
            __float2bfloat16(v.y - __bfloat162float(h1))),
        pk2(__float2bfloat16(v.z - __bfloat162float(h2)),
            __float2bfloat16(v.w - __bfloat162float(h3))));
}

// ---------------------------------------------------------------------------
// Stats combine: per row, fold 32 tile (max, expsum) -> (M, 1/S)
// ---------------------------------------------------------------------------
__global__ __launch_bounds__(256)
void stats_combine_kernel(const float* __restrict__ gmax,
                          const float* __restrict__ gsum,
                          float* __restrict__ rowM, float* __restrict__ rowI)
{
    const int row  = blockIdx.x * 8 + (threadIdx.x >> 5);
    const int lane = threadIdx.x & 31;
    float m = gmax[(long)row * NTILES_ + lane];
    float s = gsum[(long)row * NTILES_ + lane];
    float M = m;
#pragma unroll
    for (int o = 16; o; o >>= 1) M = fmaxf(M, __shfl_xor_sync(0xFFFFFFFFu, M, o));
    float sc = s * __expf(m - M);
#pragma unroll
    for (int o = 16; o; o >>= 1) sc += __shfl_xor_sync(0xFFFFFFFFu, sc, o);
    if (lane == 0) { rowM[row] = M; rowI[row] = 1.0f / sc; }
}

// ---------------------------------------------------------------------------
// bf16 hi/lo GEMM via HMMA.  D[128, NT] per CTA = A[128,K] @ B[NT,K]^T
// MODE 0: projections: bf16 A/B, +bias, write bf16 h/l
// MODE 1: scores per z=(b,h): mask+0.125, write fp32 Wt + tile stats
// MODE 2: PV per z=(b,h): A = fp32 Wt -> inline exp-normalize (writeback), B = vt h/l
// MODE 3: Wo: bf16 A/B, +bias, write fp32
// ---------------------------------------------------------------------------
template<int NT, int MODE>
__global__ void __launch_bounds__(256, 1)
hgemm_kernel(const __nv_bfloat16* __restrict__ Ah, const __nv_bfloat16* __restrict__ Al,
             const float* __restrict__ Af, int lda,
             const __nv_bfloat16* __restrict__ Bh, const __nv_bfloat16* __restrict__ Bl, int ldb,
             const float* __restrict__ bias,
             void* __restrict__ C0, void* __restrict__ C1, int ldc, int Kdim,
             const unsigned char* __restrict__ maskT,
             float* __restrict__ gmax, float* __restrict__ gsum,
             const float* __restrict__ rowM, const float* __restrict__ rowI,
             float* __restrict__ Wtw)
{
    extern __shared__ char smem[];
    constexpr int NF = NT / 16;
    constexpr unsigned MASKSZ = (MODE == 1) ? 16384u : 0u;
    constexpr unsigned ABY = 128 * 128;
    constexpr unsigned BBY = NT * 128;
    constexpr unsigned BUFSZ = 2 * ABY + 2 * BBY;

    const uint32_t sbase = smem_to_u32(smem);
    const int tid = threadIdx.x;
    const int wid = tid >> 5, lid = tid & 31;
    const int wm = wid & 3, wn = wid >> 2;           // 4(m) x 2(n)
    const int m0 = blockIdx.y * 128, n0 = blockIdx.x * NT, z = blockIdx.z;

    const __nv_bfloat16 *Aph = nullptr, *Apl = nullptr, *Bph, *Bpl;
    const float* Afp = nullptr;
    float* Wb = nullptr;
    int LDA, LDB, LDC;
    char *Cp0, *Cp1 = nullptr;
    if (MODE == 0 || MODE == 3) {
        Aph = Ah + (long)m0 * lda;  Apl = Al + (long)m0 * lda;  LDA = lda;
        Bph = Bh + (long)n0 * ldb;  Bpl = Bl + (long)n0 * ldb;  LDB = ldb;
        LDC = ldc;
        long co = (long)m0 * ldc + n0;
        if (MODE == 0) { Cp0 = (char*)((__nv_bfloat16*)C0 + co); Cp1 = (char*)((__nv_bfloat16*)C1 + co); }
        else           { Cp0 = (char*)((float*)C0 + co); }
    } else if (MODE == 1) {
        int b = z >> 4, h = z & 15;
        long ao = ((long)b * SQ_  + m0) * DQ_ + h * DH_;
        long bo = ((long)b * SKV_ + n0) * DQ_ + h * DH_;
        Aph = Ah + ao; Apl = Al + ao; LDA = DQ_;
        Bph = Bh + bo; Bpl = Bl + bo; LDB = DQ_;
        LDC = SKV_;
        Cp0 = (char*)((float*)C0 + ((long)z * SQ_ + m0) * SKV_ + n0);
    } else {
        int b = z >> 4, h = z & 15;
        long wo = ((long)z * SQ_ + m0) * SKV_;
        Afp = Af + wo;  Wb = Wtw + wo;               LDA = SKV_;
        long bo = ((long)(b * DQ_ + h * DH_)) * SKV_;
        Bph = Bh + bo; Bpl = Bl + bo;                LDB = SKV_;
        LDC = DQ_;
        long co = ((long)b * SQ_ + m0) * DQ_ + h * DH_;
        Cp0 = (char*)((__nv_bfloat16*)C0 + co); Cp1 = (char*)((__nv_bfloat16*)C1 + co);
    }

    // MODE 1: stage mask tile [q 128][kv 128] into smem (coalesced u32 loads)
    if (MODE == 1) {
        const unsigned char* msrc = maskT + ((long)(z >> 4) * SQ_ + m0) * SKV_ + n0;
#pragma unroll
        for (int it = 0; it < 16; it++) {
            int idx = it * 1024 + tid * 4;
            int r = idx >> 7, c = idx & 127;
            *(uint32_t*)(smem + idx) = *(const uint32_t*)(msrc + (long)r * SKV_ + c);
        }
    }

    // MODE 2: per-thread row stats (rows r = tid>>4 + i*16)
    float sM[MODE == 2 ? 8 : 1], sI[MODE == 2 ? 8 : 1];
    if (MODE == 2) {
        long rb = (long)z * SQ_ + m0;
#pragma unroll
        for (int i = 0; i < 8; i++) {
            int r = (tid >> 4) + i * 16;
            sM[i] = rowM[rb + r];
            sI[i] = rowI[rb + r];
        }
    }

    float dc[2 * NF][4];
#pragma unroll
    for (int i = 0; i < 2 * NF; i++)
#pragma unroll
        for (int j = 0; j < 4; j++) dc[i][j] = 0.0f;

    float4 stg[MODE == 2 ? 8 : 1];

    const int ns = Kdim >> 6;

    auto issueB = [&](int s) {
        uint32_t base = sbase + MASKSZ + (unsigned)(s & 1) * BUFSZ;
        cpa_tile<NT>(base + 2 * ABY,       Bph + (long)s * 64, LDB, tid);
        cpa_tile<NT>(base + 2 * ABY + BBY, Bpl + (long)s * 64, LDB, tid);
    };
    auto issueA = [&](int s) {
        uint32_t base = sbase + MASKSZ + (unsigned)(s & 1) * BUFSZ;
        cpa_tile<128>(base,       Aph + (long)s * 64, LDA, tid);
        cpa_tile<128>(base + ABY, Apl + (long)s * 64, LDA, tid);
    };
    auto ldgA = [&](int s) {       // MODE 2: fp32 weights -> regs
        const float* As = Afp + s * 64;
#pragma unroll
        for (int i = 0; i < 8; i++) {
            int f = tid + i * 256, r = f >> 4, cg = (f & 15) << 2;
            stg[i] = *(const float4*)(As + (long)r * LDA + cg);
        }
    };
    auto cvtstsA = [&](int s) {    // MODE 2: exp-normalize, writeback, split
        char* ah = smem + (size_t)(s & 1) * BUFSZ;
        char* al = ah + ABY;
        float* wb = Wb + s * 64;
#pragma unroll
        for (int i = 0; i < 8; i++) {
            int f = tid + i * 256, r = f >> 4, cg = (f & 15) << 2;
            float4 v = stg[i];
            float4 w;
            w.x = __expf(v.x - sM[i]) * sI[i];
            w.y = __expf(v.y - sM[i]) * sI[i];
            w.z = __expf(v.z - sM[i]) * sI[i];
            w.w = __expf(v.w - sM[i]) * sI[i];
            *(float4*)(wb + (long)r * LDA + cg) = w;
            cvt1(w, ah, al, r, cg);
        }
    };

    auto compute = [&](int buf) {
        const uint32_t sA  = sbase + MASKSZ + (unsigned)buf * BUFSZ;
        const uint32_t sAl = sA + ABY;
        const uint32_t sB  = sA + 2 * ABY;
        const uint32_t sBl = sB + BBY;
        const int lr = lid & 15, hsel = (lid >> 4) << 4;
#pragma unroll
        for (int ks = 0; ks < 4; ks++) {
            const int kb = ks * 32 + hsel;
            uint32_t aH[2][4], aL[2][4];
#pragma unroll
            for (int i = 0; i < 2; i++) {
                unsigned off = SWZ((unsigned)((wm * 32 + i * 16 + lr) * 128 + kb));
                ldm_x4(sA + off, aH[i]);
                ldm_x4(sAl + off, aL[i]);
            }
#pragma unroll
            for (int jj = 0; jj < NF / 2; jj++) {
                unsigned off = SWZ((unsigned)((wn * (NT / 2) + jj * 16 + lr) * 128 + kb));
                uint32_t bH[4], bL[4];
                ldm_x4(sB + off, bH);
                ldm_x4(sBl + off, bL);
#pragma unroll
                for (int i = 0; i < 2; i++) {
#pragma unroll
                    for (int t = 0; t < 2; t++) {
                        float* d = dc[i * NF + jj * 2 + t];
                        mma_bf16(d, aH[i], bH[t], bH[t + 2]);
                        mma_bf16(d, aH[i], bL[t], bL[t + 2]);
                        mma_bf16(d, aL[i], bH[t], bH[t + 2]);
                    }
                }
            }
        }
    };

    if (MODE == 2) {
        ldgA(0);
        issueB(0);
        asm volatile("cp.async.commit_group;" ::: "memory");
        cvtstsA(0);
        for (int s = 0; s < ns; s++) {
            if (s + 1 < ns) {
                ldgA(s + 1);
                issueB(s + 1);
                asm volatile("cp.async.commit_group;" ::: "memory");
                asm volatile("cp.async.wait_group 1;" ::: "memory");
            } else {
                asm volatile("cp.async.wait_group 0;" ::: "memory");
            }
            __syncthreads();
            compute(s & 1);
            if (s + 1 < ns) cvtstsA(s + 1);
            __syncthreads();
        }
    } else {
        issueA(0); issueB(0);
        asm volatile("cp.async.commit_group;" ::: "memory");
        for (int s = 0; s < ns; s++) {
            if (s + 1 < ns) {
                issueA(s + 1); issueB(s + 1);
                asm volatile("cp.async.commit_group;" ::: "memory");
                asm volatile("cp.async.wait_group 1;" ::: "memory");
            } else {
                asm volatile("cp.async.wait_group 0;" ::: "memory");
            }
            __syncthreads();
            compute(s & 1);
            __syncthreads();
        }
    }

    // ---- epilogue ----
    if (MODE == 1) {
        // mask + scale in registers; write Wt; per-row tile stats
        const unsigned char* mk = (const unsigned char*)smem;
        float* pm = (float*)(smem + MASKSZ);         // [2][128]
        float* ps = pm + 256;                        // [2][128]
        float* cm = ps + 256;                        // [128]
        float* cp = (float*)Cp0;
        float rmax[2][2];
#pragma unroll
        for (int i = 0; i < 2; i++) {
            rmax[i][0] = -3.4e38f; rmax[i][1] = -3.4e38f;
            int rl = wm * 32 + i * 16 + (lid >> 2);
#pragma unroll
            for (int f = 0; f < NF; f++) {
                int cl = wn * (NT / 2) + f * 8 + ((lid & 3) << 1);
                float* d = dc[i * NF + f];
                d[0] = mk[rl * 128 + cl]           ? -1.0e9f : d[0] * 0.125f;
                d[1] = mk[rl * 128 + cl + 1]       ? -1.0e9f : d[1] * 0.125f;
                d[2] = mk[(rl + 8) * 128 + cl]     ? -1.0e9f : d[2] * 0.125f;
                d[3] = mk[(rl + 8) * 128 + cl + 1] ? -1.0e9f : d[3] * 0.125f;
                rmax[i][0] = fmaxf(rmax[i][0], fmaxf(d[0], d[1]));
                rmax[i][1] = fmaxf(rmax[i][1], fmaxf(d[2], d[3]));
                *(float2*)(cp + (long)rl * LDC + cl)       = make_float2(d[0], d[1]);
                *(float2*)(cp + (long)(rl + 8) * LDC + cl) = make_float2(d[2], d[3]);
            }
        }
#pragma unroll
        for (int i = 0; i < 2; i++)
#pragma unroll
            for (int s = 0; s < 2; s++) {
                float m = rmax[i][s];
                m = fmaxf(m, __shfl_xor_sync(0xFFFFFFFFu, m, 1));
                m = fmaxf(m, __shfl_xor_sync(0xFFFFFFFFu, m, 2));
                rmax[i][s] = m;
            }
        if ((lid & 3) == 0) {
#pragma unroll
            for (int i = 0; i < 2; i++)
#pragma unroll
                for (int s = 0; s < 2; s++)
                    pm[wn * 128 + wm * 32 + i * 16 + (lid >> 2) + s * 8] = rmax[i][s];
        }
        __syncthreads();
        if (tid < 128) cm[tid] = fmaxf(pm[tid], pm[128 + tid]);
        __syncthreads();
        float rsum[2][2] = {{0.0f, 0.0f}, {0.0f, 0.0f}};
#pragma unroll
        for (int i = 0; i < 2; i++) {
            int rl = wm * 32 + i * 16 + (lid >> 2);
            float mv0 = cm[rl], mv1 = cm[rl + 8];
#pragma unroll
            for (int f = 0; f < NF; f++) {
                float* d = dc[i * NF + f];
                rsum[i][0] += __expf(d[0] - mv0) + __expf(d[1] - mv0);
                rsum[i][1] += __expf(d[2] - mv1) + __expf(d[3] - mv1);
            }
        }
#pragma unroll
        for (int i = 0; i < 2; i++)
#pragma unroll
            for (int s = 0; s < 2; s++) {
                float v = rsum[i][s];
                v += __shfl_xor_sync(0xFFFFFFFFu, v, 1);
                v += __shfl_xor_sync(0xFFFFFFFFu, v, 2);
                rsum[i][s] = v;
            }
        if ((lid & 3) == 0) {
#pragma unroll
            for (int i = 0; i < 2; i++)
#pragma unroll
                for (int s = 0; s < 2; s++)
                    ps[wn * 128 + wm * 32 + i * 16 + (lid >> 2) + s * 8] = rsum[i][s];
        }
        __syncthreads();
        if (tid < 128) {
            long rg = (long)z * SQ_ + m0 + tid;
            gmax[rg * NTILES_ + blockIdx.x] = cm[tid];
            gsum[rg * NTILES_ + blockIdx.x] = ps[tid] + ps[128 + tid];
        }
        return;
    }

#pragma unroll
    for (int i = 0; i < 2; i++) {
#pragma unroll
        for (int f = 0; f < NF; f++) {
            const float* d = dc[i * NF + f];
            int rl = wm * 32 + i * 16 + (lid >> 2);
            int cl = wn * (NT / 2) + f * 8 + ((lid & 3) << 1);
            if (MODE == 0 || MODE == 2) {
                float bx = 0.0f, by = 0.0f;
                if (MODE == 0) { float2 bb = *(const float2*)(bias + n0 + cl); bx = bb.x; by = bb.y; }
                float v0 = d[0] + bx, v1 = d[1] + by;
                float v2 = d[2] + bx, v3 = d[3] + by;
                __nv_bfloat16 h0 = __float2bfloat16(v0), h1 = __float2bfloat16(v1);
                __nv_bfloat16 h2 = __float2bfloat16(v2), h3 = __float2bfloat16(v3);
                __nv_bfloat16* ch = (__nv_bfloat16*)Cp0;
                __nv_bfloat16* cll = (__nv_bfloat16*)Cp1;
                *(uint32_t*)(ch + (long)rl * LDC + cl)       = pk2(h0, h1);
                *(uint32_t*)(ch + (long)(rl + 8) * LDC + cl) = pk2(h2, h3);
                *(uint32_t*)(cll + (long)rl * LDC + cl) =
                    pk2(__float2bfloat16(v0 - __bfloat162float(h0)),
                        __float2bfloat16(v1 - __bfloat162float(h1)));
                *(uint32_t*)(cll + (long)(rl + 8) * LDC + cl) =
                    pk2(__float2bfloat16(v2 - __bfloat162float(h2)),
                        __float2bfloat16(v3 - __bfloat162float(h3)));
            } else {
                float2 bb = *(const float2*)(bias + n0 + cl);
                float* cp = (float*)Cp0;
                *(float2*)(cp + (long)rl * LDC + cl) =
                    make_float2(d[0] + bb.x, d[1] + bb.y);
                *(float2*)(cp + (long)(rl + 8) * LDC + cl) =
                    make_float2(d[2] + bb.x, d[3] + bb.y);
            }
        }
    }
}

// ---------------------------------------------------------------------------
// bf16 transpose: v h/l [b][kv][ch] -> vt h/l [b][ch][kv]
// ---------------------------------------------------------------------------
__global__ __launch_bounds__(256)
void transpose_bf16_kernel(const __nv_bfloat16* __restrict__ vh,
                           const __nv_bfloat16* __restrict__ vl,
                           __nv_bfloat16* __restrict__ vth,
                           __nv_bfloat16* __restrict__ vtl)
{
    __shared__ __nv_bfloat16 th[32][34], tl[32][34];
    const int b   = blockIdx.z;
    const int kv0 = blockIdx.x * 32, ch0 = blockIdx.y * 32;
    const int x = threadIdx.x, y = threadIdx.y;      // 32 x 8
#pragma unroll
    for (int i = y; i < 32; i += 8) {
        long src = ((long)b * SKV_ + kv0 + i) * DQ_ + ch0 + x;
        th[i][x] = vh[src];
        tl[i][x] = vl[src];
    }
    __syncthreads();
#pragma unroll
    for (int i = y; i < 32; i += 8) {
        long dst = ((long)b * DQ_ + ch0 + i) * SKV_ + kv0 + x;
        vth[dst] = th[x][i];
        vtl[dst] = tl[x][i];
    }
}

// ---------------------------------------------------------------------------
// Launch
// ---------------------------------------------------------------------------
extern "C" void kernel_launch(void* const* d_in, const int* in_sizes, int n_in,
                              void* d_out, int out_size)
{
    (void)in_sizes; (void)n_in; (void)out_size;

    const float* Q   = (const float*)d_in[0];
    const float* K   = (const float*)d_in[1];
    const float* V   = (const float*)d_in[2];
    const void*  Msk = d_in[3];
    const float* Wq  = (const float*)d_in[4];
    const float* bq  = (const float*)d_in[5];
    const float* Wk  = (const float*)d_in[6];
    const float* bk  = (const float*)d_in[7];
    const float* Wv  = (const float*)d_in[8];
    const float* bv  = (const float*)d_in[9];
    const float* Wo  = (const float*)d_in[10];
    const float* bo  = (const float*)d_in[11];

    float* out = (float*)d_out;                       // [B,SQ,DOUT]
    float* Wt  = out + (size_t)B_ * SQ_ * DOUT_;      // [B,H,SQ,SKV]

    __nv_bfloat16 *sqh, *sql, *skh, *skl, *svh, *svl;
    __nv_bfloat16 *wqh, *wql, *wkh, *wkl, *wvh, *wvl, *woh, *wol;
    __nv_bfloat16 *qh, *ql, *kh, *kl, *vh, *vl, *vth, *vtl, *ath, *atl;
    unsigned char* mT;
    float *gmx, *gsm, *rM, *rI;
    cudaGetSymbolAddress((void**)&sqh, g_sqh); cudaGetSymbolAddress((void**)&sql, g_sql);
    cudaGetSymbolAddress((void**)&skh, g_skh); cudaGetSymbolAddress((void**)&skl, g_skl);
    cudaGetSymbolAddress((void**)&svh, g_svh); cudaGetSymbolAddress((void**)&svl, g_svl);
    cudaGetSymbolAddress((void**)&wqh, g_wqh); cudaGetSymbolAddress((void**)&wql, g_wql);
    cudaGetSymbolAddress((void**)&wkh, g_wkh); cudaGetSymbolAddress((void**)&wkl, g_wkl);
    cudaGetSymbolAddress((void**)&wvh, g_wvh); cudaGetSymbolAddress((void**)&wvl, g_wvl);
    cudaGetSymbolAddress((void**)&woh, g_woh); cudaGetSymbolAddress((void**)&wol, g_wol);
    cudaGetSymbolAddress((void**)&qh,  g_qh);  cudaGetSymbolAddress((void**)&ql,  g_ql);
    cudaGetSymbolAddress((void**)&kh,  g_kh);  cudaGetSymbolAddress((void**)&kl,  g_kl);
    cudaGetSymbolAddress((void**)&vh,  g_vh);  cudaGetSymbolAddress((void**)&vl,  g_vl);
    cudaGetSymbolAddress((void**)&vth, g_vth); cudaGetSymbolAddress((void**)&vtl, g_vtl);
    cudaGetSymbolAddress((void**)&ath, g_ath); cudaGetSymbolAddress((void**)&atl, g_atl);
    cudaGetSymbolAddress((void**)&mT,  g_maskT);
    cudaGetSymbolAddress((void**)&gmx, g_gmax); cudaGetSymbolAddress((void**)&gsm, g_gsum);
    cudaGetSymbolAddress((void**)&rM,  g_rowM); cudaGetSymbolAddress((void**)&rI,  g_rowI);

    const int SM0 = 2 * 65536;            // modes 0 (2-stage, NT128)
    const int SM1 = 16384 + 65536;        // mode 1 (mask + 1-stage NT128)
    const int SM2 = 2 * 49152;            // modes 2,3 (2-stage, NT64)
    cudaFuncSetAttribute(hgemm_kernel<128, 0>, cudaFuncAttributeMaxDynamicSharedMemorySize, SM0);
    cudaFuncSetAttribute(hgemm_kernel<128, 1>, cudaFuncAttributeMaxDynamicSharedMemorySize, SM1);
    cudaFuncSetAttribute(hgemm_kernel<64, 2>,  cudaFuncAttributeMaxDynamicSharedMemorySize, SM2);
    cudaFuncSetAttribute(hgemm_kernel<64, 3>,  cudaFuncAttributeMaxDynamicSharedMemorySize, SM2);

    // 0) probe + operand splits + mask transpose
    probe_mask_kernel<<<1, 1>>>((const unsigned int*)Msk);
    split_kernel<<<(B_ * SQ_ * DQ_)   / 1024, 256>>>(Q,  sqh, sql);
    split_kernel<<<(B_ * SKV_ * DKV_) / 1024, 256>>>(K, skh, skl);
    split_kernel<<<(B_ * SKV_ * DKV_) / 1024, 256>>>(V, svh, svl);
    split_kernel<<<(DQ_ * DQ_)   / 1024, 256>>>(Wq, wqh, wql);
    split_kernel<<<(DQ_ * DKV_)  / 1024, 256>>>(Wk, wkh, wkl);
    split_kernel<<<(DQ_ * DKV_)  / 1024, 256>>>(Wv, wvh, wvl);
    split_kernel<<<(DOUT_ * DQ_) / 1024, 256>>>(Wo, woh, wol);
    transpose_mask_kernel<<<dim3(SKV_ / 32, SQ_ / 32, B_), dim3(32, 8)>>>(Msk, mT);

    // 1) projections -> bf16 h/l
    hgemm_kernel<128, 0><<<dim3(DQ_ / 128, (B_ * SQ_) / 128, 1), 256, SM0>>>(
        sqh, sql, nullptr, DQ_, wqh, wql, DQ_, bq, qh, ql, DQ_, DQ_,
        nullptr, nullptr, nullptr, nullptr, nullptr, nullptr);
    hgemm_kernel<128, 0><<<dim3(DQ_ / 128, (B_ * SKV_) / 128, 1), 256, SM0>>>(
        skh, skl, nullptr, DKV_, wkh, wkl, DKV_, bk, kh, kl, DQ_, DKV_,
        nullptr, nullptr, nullptr, nullptr, nullptr, nullptr);
    hgemm_kernel<128, 0><<<dim3(DQ_ / 128, (B_ * SKV_) / 128, 1), 256, SM0>>>(
        svh, svl, nullptr, DKV_, wvh, wvl, DKV_, bv, vh, vl, DQ_, DKV_,
        nullptr, nullptr, nullptr, nullptr, nullptr, nullptr);

    // 1b) transpose projected V (bf16 h/l)
    transpose_bf16_kernel<<<dim3(SKV_ / 32, DQ_ / 32, B_), dim3(32, 8)>>>(
        vh, vl, vth, vtl);

    // 2) masked scores -> fp32 Wt + per-tile softmax stats
    hgemm_kernel<128, 1><<<dim3(SKV_ / 128, SQ_ / 128, B_ * H_), 256, SM1>>>(
        qh, ql, nullptr, 0, kh, kl, 0, nullptr, Wt, nullptr, 0, DH_,
        mT, gmx, gsm, nullptr, nullptr, nullptr);

    // 3) fold tile stats -> per-row (M, 1/S)
    stats_combine_kernel<<<NROWS_ / 8, 256>>>(gmx, gsm, rM, rI);

    // 4) PV: exp-normalize Wt inline (writeback normalized weights), GEMM with V^T
    hgemm_kernel<64, 2><<<dim3(1, SQ_ / 128, B_ * H_), 256, SM2>>>(
        nullptr, nullptr, Wt, 0, vth, vtl, 0, nullptr, ath, atl, 0, SKV_,
        nullptr, nullptr, nullptr, rM, rI, Wt);

    // 5) output projection -> fp32 front of d_out
    hgemm_kernel<64, 3><<<dim3(DOUT_ / 64, (B_ * SQ_) / 128, 1), 256, SM2>>>(
        ath, atl, nullptr, DQ_, woh, wol, DQ_, bo, out, nullptr, DOUT_, DQ_,
        nullptr, nullptr, nullptr, nullptr, nullptr, nullptr);
}

// round 10
// speedup vs baseline: 1.6802x; 1.1221x over previous
#include <cuda_runtime.h>
#include <cuda_bf16.h>
#include <cstdint>
#include <math.h>

// Problem constants
#define B_    4
#define SQ_   1024
#define SKV_  4096
#define DQ_   1024
#define DKV_  768
#define H_    16
#define DH_   64
#define DOUT_ 256

#define SWZ(o) ((o) ^ (((o) >> 3) & 0x70))

// ---------------------------------------------------------------------------
// Scratch (static device globals; bf16 buffers 16B aligned for cp.async)
// ---------------------------------------------------------------------------
#define AL16 __align__(16)
// raw-input splits
__device__ AL16 __nv_bfloat16 g_sqh[(size_t)B_ * SQ_  * DQ_ ], g_sql[(size_t)B_ * SQ_  * DQ_ ];
__device__ AL16 __nv_bfloat16 g_skh[(size_t)B_ * SKV_ * DKV_], g_skl[(size_t)B_ * SKV_ * DKV_];
__device__ AL16 __nv_bfloat16 g_svh[(size_t)B_ * SKV_ * DKV_], g_svl[(size_t)B_ * SKV_ * DKV_];
// weight splits
__device__ AL16 __nv_bfloat16 g_wqh[DQ_ * DQ_ ],  g_wql[DQ_ * DQ_ ];
__device__ AL16 __nv_bfloat16 g_wkh[DQ_ * DKV_],  g_wkl[DQ_ * DKV_];
__device__ AL16 __nv_bfloat16 g_wvh[DQ_ * DKV_],  g_wvl[DQ_ * DKV_];
__device__ AL16 __nv_bfloat16 g_woh[DOUT_ * DQ_], g_wol[DOUT_ * DQ_];
// projected tensors (bf16 hi/lo)
__device__ AL16 __nv_bfloat16 g_qh [(size_t)B_ * SQ_  * DQ_], g_ql [(size_t)B_ * SQ_  * DQ_];
__device__ AL16 __nv_bfloat16 g_kh [(size_t)B_ * SKV_ * DQ_], g_kl [(size_t)B_ * SKV_ * DQ_];
__device__ AL16 __nv_bfloat16 g_vh [(size_t)B_ * SKV_ * DQ_], g_vl [(size_t)B_ * SKV_ * DQ_];
__device__ AL16 __nv_bfloat16 g_vth[(size_t)B_ * DQ_ * SKV_], g_vtl[(size_t)B_ * DQ_ * SKV_];
// attention output pre-Wo (bf16 hi/lo)
__device__ AL16 __nv_bfloat16 g_ath[(size_t)B_ * SQ_ * DQ_], g_atl[(size_t)B_ * SQ_ * DQ_];
// transposed mask u8 [b][q][kv]
__device__ AL16 unsigned char g_maskT[(size_t)B_ * SQ_ * SKV_];
// softmax stats: per (row, kv-tile of 64) and per row
#define NROWS_ (B_ * H_ * SQ_)
#define NTILES_ (SKV_ / 64)
__device__ AL16 float g_gmax[(size_t)NROWS_ * NTILES_];
__device__ AL16 float g_gsum[(size_t)NROWS_ * NTILES_];
__device__ AL16 float g_rowM[NROWS_];
__device__ AL16 float g_rowI[NROWS_];
__device__ int g_mask_flag;

// ---------------------------------------------------------------------------
// Mask dtype probe
// ---------------------------------------------------------------------------
__global__ void probe_mask_kernel(const unsigned int* __restrict__ m)
{
    if (blockIdx.x != 0 || threadIdx.x != 0) return;
    int is_i32 = 1, is_f32 = 1;
    for (int i = 0; i < 4096; i++) {
        unsigned v = m[i];
        if (v > 1u) is_i32 = 0;
        if (v != 0u && v != 0x3F800000u) is_f32 = 0;
    }
    g_mask_flag = is_i32 ? 1 : (is_f32 ? 2 : 0);
}

__device__ __forceinline__ bool read_mask(const void* m, long i, int flag)
{
    if (flag == 1) return ((const int*)m)[i] != 0;
    if (flag == 2) return ((const float*)m)[i] != 0.0f;
    return ((const unsigned char*)m)[i] != 0;
}

// ---------------------------------------------------------------------------
// Mask transpose: mask[b][kv][q] (any dtype) -> u8 maskT[b][q][kv]
// ---------------------------------------------------------------------------
__global__ __launch_bounds__(256)
void transpose_mask_kernel(const void* __restrict__ mask,
                           unsigned char* __restrict__ maskT)
{
    __shared__ unsigned char t[32][33];
    const int b   = blockIdx.z;
    const int kv0 = blockIdx.x * 32, q0 = blockIdx.y * 32;
    const int x = threadIdx.x, y = threadIdx.y;      // 32 x 8
    const int flag = g_mask_flag;
#pragma unroll
    for (int i = y; i < 32; i += 8)
        t[i][x] = read_mask(mask, ((long)b * SKV_ + kv0 + i) * SQ_ + q0 + x, flag) ? 1 : 0;
    __syncthreads();
#pragma unroll
    for (int i = y; i < 32; i += 8)
        maskT[((long)b * SQ_ + q0 + i) * SKV_ + kv0 + x] = t[x][i];
}

// ---------------------------------------------------------------------------
// Primitives
// ---------------------------------------------------------------------------
__device__ __forceinline__ uint32_t smem_to_u32(const void* p) {
    uint32_t a;
    asm("{ .reg .u64 t; cvta.to.shared.u64 t, %1; cvt.u32.u64 %0, t; }"
        : "=r"(a) : "l"(p));
    return a;
}

__device__ __forceinline__ void ldm_x4(uint32_t addr, uint32_t* r) {
    asm volatile("ldmatrix.sync.aligned.m8n8.x4.shared.b16 {%0,%1,%2,%3}, [%4];"
                 : "=r"(r[0]), "=r"(r[1]), "=r"(r[2]), "=r"(r[3]) : "r"(addr));
}

__device__ __forceinline__ void mma_bf16(float* d, const uint32_t* a,
                                         uint32_t b0, uint32_t b1) {
    asm volatile(
        "mma.sync.aligned.m16n8k16.row.col.f32.bf16.bf16.f32 "
        "{%0,%1,%2,%3}, {%4,%5,%6,%7}, {%8,%9}, {%0,%1,%2,%3};"
        : "+f"(d[0]), "+f"(d[1]), "+f"(d[2]), "+f"(d[3])
        : "r"(a[0]), "r"(a[1]), "r"(a[2]), "r"(a[3]), "r"(b0), "r"(b1));
}

__device__ __forceinline__ uint32_t pk2(__nv_bfloat16 a, __nv_bfloat16 b)
{
    return (uint32_t)__bfloat16_as_ushort(a) | ((uint32_t)__bfloat16_as_ushort(b) << 16);
}

__device__ __forceinline__ void cvt1(float4 v, char* hb, char* lb, int r, int cg)
{
    __nv_bfloat16 h0 = __float2bfloat16(v.x);
    __nv_bfloat16 h1 = __float2bfloat16(v.y);
    __nv_bfloat16 h2 = __float2bfloat16(v.z);
    __nv_bfloat16 h3 = __float2bfloat16(v.w);
    __nv_bfloat16 l0 = __float2bfloat16(v.x - __bfloat162float(h0));
    __nv_bfloat16 l1 = __float2bfloat16(v.y - __bfloat162float(h1));
    __nv_bfloat16 l2 = __float2bfloat16(v.z - __bfloat162float(h2));
    __nv_bfloat16 l3 = __float2bfloat16(v.w - __bfloat162float(h3));
    unsigned off = SWZ((unsigned)(r * 128 + (cg << 1)));
    *(uint2*)(hb + off) = make_uint2(pk2(h0, h1), pk2(h2, h3));
    *(uint2*)(lb + off) = make_uint2(pk2(l0, l1), pk2(l2, l3));
}

// cp.async a ROWSx64-bf16 tile (rows of 128B) into SW128 swizzled smem
template<int ROWS>
__device__ __forceinline__ void cpa_tile(uint32_t dst, const __nv_bfloat16* src,
                                         int ld, int tid)
{
#pragma unroll
    for (int i = 0; i < ROWS / 32; i++) {
        int f = tid + i * 256;
        int r = f >> 3, c = f & 7;
        uint32_t d = dst + SWZ((unsigned)(r * 128 + c * 16));
        const void* s = src + (long)r * ld + c * 8;
        asm volatile("cp.async.cg.shared.global [%0], [%1], 16;" :: "r"(d), "l"(s));
    }
}

// ---------------------------------------------------------------------------
// fp32 -> bf16 hi/lo split (elementwise, n divisible by 1024)
// ---------------------------------------------------------------------------
__global__ __launch_bounds__(256)
void split_kernel(const float* __restrict__ src,
                  __nv_bfloat16* __restrict__ h, __nv_bfloat16* __restrict__ l)
{
    long i = ((long)blockIdx.x * 256 + threadIdx.x) * 4;
    float4 v = *(const float4*)(src + i);
    __nv_bfloat16 h0 = __float2bfloat16(v.x), h1 = __float2bfloat16(v.y);
    __nv_bfloat16 h2 = __float2bfloat16(v.z), h3 = __float2bfloat16(v.w);
    *(uint2*)(h + i) = make_uint2(pk2(h0, h1), pk2(h2, h3));
    *(uint2*)(l + i) = make_uint2(
        pk2(__float2bfloat16(v.x - __bfloat162float(h0)),
            __float2bfloat16(v.y - __bfloat162float(h1))),
        pk2(__float2bfloat16(v.z - __bfloat162float(h2)),
            __float2bfloat16(v.w - __bfloat162float(h3))));
}

// ---------------------------------------------------------------------------
// Stats combine: per row, fold 64 tile (max, expsum) -> (M, 1/S)
// ---------------------------------------------------------------------------
__global__ __launch_bounds__(256)
void stats_combine_kernel(const float* __restrict__ gmax,
                          const float* __restrict__ gsum,
                          float* __restrict__ rowM, float* __restrict__ rowI)
{
    const int row  = blockIdx.x * 8 + (threadIdx.x >> 5);
    const int lane = threadIdx.x & 31;
    float m0 = gmax[(long)row * NTILES_ + lane];
    float m1 = gmax[(long)row * NTILES_ + lane + 32];
    float s0 = gsum[(long)row * NTILES_ + lane];
    float s1 = gsum[(long)row * NTILES_ + lane + 32];
    float M = fmaxf(m0, m1);
#pragma unroll
    for (int o = 16; o; o >>= 1) M = fmaxf(M, __shfl_xor_sync(0xFFFFFFFFu, M, o));
    float sc = s0 * __expf(m0 - M) + s1 * __expf(m1 - M);
#pragma unroll
    for (int o = 16; o; o >>= 1) sc += __shfl_xor_sync(0xFFFFFFFFu, sc, o);
    if (lane == 0) { rowM[row] = M; rowI[row] = 1.0f / sc; }
}

// ---------------------------------------------------------------------------
// bf16 hi/lo GEMM via HMMA.  D[128, 64] per CTA = A[128,K] @ B[64,K]^T
// MODE 0: projections: bf16 A/B, +bias, write bf16 h/l
// MODE 1: scores per z=(b,h): mask+0.125, write fp32 Wt + tile stats
// MODE 2: PV per z=(b,h): A = fp32 Wt -> inline exp-normalize (writeback), B = vt h/l
// MODE 3: Wo: bf16 A/B, +bias, write fp32
// NT=64 everywhere -> 96KB smem (2-stage) -> 2+ CTAs/SM with regs <= 128
// ---------------------------------------------------------------------------
template<int MODE>
__global__ void __launch_bounds__(256, 2)
hgemm_kernel(const __nv_bfloat16* __restrict__ Ah, const __nv_bfloat16* __restrict__ Al,
             const float* __restrict__ Af, int lda,
             const __nv_bfloat16* __restrict__ Bh, const __nv_bfloat16* __restrict__ Bl, int ldb,
             const float* __restrict__ bias,
             void* __restrict__ C0, void* __restrict__ C1, int ldc, int Kdim,
             const unsigned char* __restrict__ maskT,
             float* __restrict__ gmax, float* __restrict__ gsum,
             const float* __restrict__ rowM, const float* __restrict__ rowI,
             float* __restrict__ Wtw)
{
    extern __shared__ char smem[];
    constexpr int NT = 64;
    constexpr int NF = NT / 16;                      // 4
    constexpr unsigned MASKSZ = (MODE == 1) ? 8192u : 0u;
    constexpr unsigned ABY = 128 * 128;
    constexpr unsigned BBY = NT * 128;
    constexpr unsigned BUFSZ = 2 * ABY + 2 * BBY;    // 49152

    const uint32_t sbase = smem_to_u32(smem);
    const int tid = threadIdx.x;
    const int wid = tid >> 5, lid = tid & 31;
    const int wm = wid & 3, wn = wid >> 2;           // 4(m) x 2(n)
    const int m0 = blockIdx.y * 128, n0 = blockIdx.x * NT, z = blockIdx.z;

    const __nv_bfloat16 *Aph = nullptr, *Apl = nullptr, *Bph, *Bpl;
    const float* Afp = nullptr;
    float* Wb = nullptr;
    int LDA, LDB, LDC;
    char *Cp0, *Cp1 = nullptr;
    if (MODE == 0 || MODE == 3) {
        Aph = Ah + (long)m0 * lda;  Apl = Al + (long)m0 * lda;  LDA = lda;
        Bph = Bh + (long)n0 * ldb;  Bpl = Bl + (long)n0 * ldb;  LDB = ldb;
        LDC = ldc;
        long co = (long)m0 * ldc + n0;
        if (MODE == 0) { Cp0 = (char*)((__nv_bfloat16*)C0 + co); Cp1 = (char*)((__nv_bfloat16*)C1 + co); }
        else           { Cp0 = (char*)((float*)C0 + co); }
    } else if (MODE == 1) {
        int b = z >> 4, h = z & 15;
        long ao = ((long)b * SQ_  + m0) * DQ_ + h * DH_;
        long bo = ((long)b * SKV_ + n0) * DQ_ + h * DH_;
        Aph = Ah + ao; Apl = Al + ao; LDA = DQ_;
        Bph = Bh + bo; Bpl = Bl + bo; LDB = DQ_;
        LDC = SKV_;
        Cp0 = (char*)((float*)C0 + ((long)z * SQ_ + m0) * SKV_ + n0);
    } else {
        int b = z >> 4, h = z & 15;
        long wo = ((long)z * SQ_ + m0) * SKV_;
        Afp = Af + wo;  Wb = Wtw + wo;               LDA = SKV_;
        long bo = ((long)(b * DQ_ + h * DH_)) * SKV_;
        Bph = Bh + bo; Bpl = Bl + bo;                LDB = SKV_;
        LDC = DQ_;
        long co = ((long)b * SQ_ + m0) * DQ_ + h * DH_;
        Cp0 = (char*)((__nv_bfloat16*)C0 + co); Cp1 = (char*)((__nv_bfloat16*)C1 + co);
    }

    // MODE 1: stage mask tile [q 128][kv 64] into smem (coalesced u32 loads)
    if (MODE == 1) {
        const unsigned char* msrc = maskT + ((long)(z >> 4) * SQ_ + m0) * SKV_ + n0;
#pragma unroll
        for (int it = 0; it < 8; it++) {
            int idx = it * 1024 + tid * 4;
            int r = idx >> 6, c = idx & 63;
            *(uint32_t*)(smem + idx) = *(const uint32_t*)(msrc + (long)r * SKV_ + c);
        }
    }

    // MODE 2: per-thread row stats (rows r = tid>>4 + i*16)
    float sM[MODE == 2 ? 8 : 1], sI[MODE == 2 ? 8 : 1];
    if (MODE == 2) {
        long rb = (long)z * SQ_ + m0;
#pragma unroll
        for (int i = 0; i < 8; i++) {
            int r = (tid >> 4) + i * 16;
            sM[i] = rowM[rb + r];
            sI[i] = rowI[rb + r];
        }
    }

    float dc[2 * NF][4];
#pragma unroll
    for (int i = 0; i < 2 * NF; i++)
#pragma unroll
        for (int j = 0; j < 4; j++) dc[i][j] = 0.0f;

    float4 stg[MODE == 2 ? 8 : 1];

    const int ns = Kdim >> 6;

    auto issueB = [&](int s) {
        uint32_t base = sbase + MASKSZ + (unsigned)(s & 1) * BUFSZ;
        cpa_tile<NT>(base + 2 * ABY,       Bph + (long)s * 64, LDB, tid);
        cpa_tile<NT>(base + 2 * ABY + BBY, Bpl + (long)s * 64, LDB, tid);
    };
    auto issueA = [&](int s) {
        uint32_t base = sbase + MASKSZ + (unsigned)(s & 1) * BUFSZ;
        cpa_tile<128>(base,       Aph + (long)s * 64, LDA, tid);
        cpa_tile<128>(base + ABY, Apl + (long)s * 64, LDA, tid);
    };
    auto ldgA = [&](int s) {       // MODE 2: fp32 weights -> regs
        const float* As = Afp + s * 64;
#pragma unroll
        for (int i = 0; i < 8; i++) {
            int f = tid + i * 256, r = f >> 4, cg = (f & 15) << 2;
            stg[i] = *(const float4*)(As + (long)r * LDA + cg);
        }
    };
    auto cvtstsA = [&](int s) {    // MODE 2: exp-normalize, writeback, split
        char* ah = smem + (size_t)(s & 1) * BUFSZ;
        char* al = ah + ABY;
        float* wb = Wb + s * 64;
#pragma unroll
        for (int i = 0; i < 8; i++) {
            int f = tid + i * 256, r = f >> 4, cg = (f & 15) << 2;
            float4 v = stg[i];
            float4 w;
            w.x = __expf(v.x - sM[i]) * sI[i];
            w.y = __expf(v.y - sM[i]) * sI[i];
            w.z = __expf(v.z - sM[i]) * sI[i];
            w.w = __expf(v.w - sM[i]) * sI[i];
            *(float4*)(wb + (long)r * LDA + cg) = w;
            cvt1(w, ah, al, r, cg);
        }
    };

    auto compute = [&](int buf) {
        const uint32_t sA  = sbase + MASKSZ + (unsigned)buf * BUFSZ;
        const uint32_t sAl = sA + ABY;
        const uint32_t sB  = sA + 2 * ABY;
        const uint32_t sBl = sB + BBY;
        const int lr = lid & 15, hsel = (lid >> 4) << 4;
#pragma unroll
        for (int ks = 0; ks < 4; ks++) {
            const int kb = ks * 32 + hsel;
            uint32_t aH[2][4], aL[2][4];
#pragma unroll
            for (int i = 0; i < 2; i++) {
                unsigned off = SWZ((unsigned)((wm * 32 + i * 16 + lr) * 128 + kb));
                ldm_x4(sA + off, aH[i]);
                ldm_x4(sAl + off, aL[i]);
            }
#pragma unroll
            for (int jj = 0; jj < NF / 2; jj++) {
                unsigned off = SWZ((unsigned)((wn * (NT / 2) + jj * 16 + lr) * 128 + kb));
                uint32_t bH[4], bL[4];
                ldm_x4(sB + off, bH);
                ldm_x4(sBl + off, bL);
#pragma unroll
                for (int i = 0; i < 2; i++) {
#pragma unroll
                    for (int t = 0; t < 2; t++) {
                        float* d = dc[i * NF + jj * 2 + t];
                        mma_bf16(d, aH[i], bH[t], bH[t + 2]);
                        mma_bf16(d, aH[i], bL[t], bL[t + 2]);
                        mma_bf16(d, aL[i], bH[t], bH[t + 2]);
                    }
                }
            }
        }
    };

    if (MODE == 2) {
        ldgA(0);
        issueB(0);
        asm volatile("cp.async.commit_group;" ::: "memory");
        cvtstsA(0);
        for (int s = 0; s < ns; s++) {
            if (s + 1 < ns) {
                ldgA(s + 1);
                issueB(s + 1);
                asm volatile("cp.async.commit_group;" ::: "memory");
                asm volatile("cp.async.wait_group 1;" ::: "memory");
            } else {
                asm volatile("cp.async.wait_group 0;" ::: "memory");
            }
            __syncthreads();
            compute(s & 1);
            if (s + 1 < ns) cvtstsA(s + 1);
            __syncthreads();
        }
    } else {
        issueA(0); issueB(0);
        asm volatile("cp.async.commit_group;" ::: "memory");
        for (int s = 0; s < ns; s++) {
            if (s + 1 < ns) {
                issueA(s + 1); issueB(s + 1);
                asm volatile("cp.async.commit_group;" ::: "memory");
                asm volatile("cp.async.wait_group 1;" ::: "memory");
            } else {
                asm volatile("cp.async.wait_group 0;" ::: "memory");
            }
            __syncthreads();
            compute(s & 1);
            __syncthreads();
        }
    }

    // ---- epilogue ----
    if (MODE == 1) {
        // mask + scale in registers; write Wt; per-row tile stats
        const unsigned char* mk = (const unsigned char*)smem;
        float* pm = (float*)(smem + MASKSZ);         // [2][128]
        float* ps = pm + 256;                        // [2][128]
        float* cm = ps + 256;                        // [128]
        float* cp = (float*)Cp0;
        float rmax[2][2];
#pragma unroll
        for (int i = 0; i < 2; i++) {
            rmax[i][0] = -3.4e38f; rmax[i][1] = -3.4e38f;
            int rl = wm * 32 + i * 16 + (lid >> 2);
#pragma unroll
            for (int f = 0; f < NF; f++) {
                int cl = wn * (NT / 2) + f * 8 + ((lid & 3) << 1);
                float* d = dc[i * NF + f];
                d[0] = mk[rl * 64 + cl]           ? -1.0e9f : d[0] * 0.125f;
                d[1] = mk[rl * 64 + cl + 1]       ? -1.0e9f : d[1] * 0.125f;
                d[2] = mk[(rl + 8) * 64 + cl]     ? -1.0e9f : d[2] * 0.125f;
                d[3] = mk[(rl + 8) * 64 + cl + 1] ? -1.0e9f : d[3] * 0.125f;
                rmax[i][0] = fmaxf(rmax[i][0], fmaxf(d[0], d[1]));
                rmax[i][1] = fmaxf(rmax[i][1], fmaxf(d[2], d[3]));
                *(float2*)(cp + (long)rl * LDC + cl)       = make_float2(d[0], d[1]);
                *(float2*)(cp + (long)(rl + 8) * LDC + cl) = make_float2(d[2], d[3]);
            }
        }
#pragma unroll
        for (int i = 0; i < 2; i++)
#pragma unroll
            for (int s = 0; s < 2; s++) {
                float m = rmax[i][s];
                m = fmaxf(m, __shfl_xor_sync(0xFFFFFFFFu, m, 1));
                m = fmaxf(m, __shfl_xor_sync(0xFFFFFFFFu, m, 2));
                rmax[i][s] = m;
            }
        if ((lid & 3) == 0) {
#pragma unroll
            for (int i = 0; i < 2; i++)
#pragma unroll
                for (int s = 0; s < 2; s++)
                    pm[wn * 128 + wm * 32 + i * 16 + (lid >> 2) + s * 8] = rmax[i][s];
        }
        __syncthreads();
        if (tid < 128) cm[tid] = fmaxf(pm[tid], pm[128 + tid]);
        __syncthreads();
        float rsum[2][2] = {{0.0f, 0.0f}, {0.0f, 0.0f}};
#pragma unroll
        for (int i = 0; i < 2; i++) {
            int rl = wm * 32 + i * 16 + (lid >> 2);
            float mv0 = cm[rl], mv1 = cm[rl + 8];
#pragma unroll
            for (int f = 0; f < NF; f++) {
                float* d = dc[i * NF + f];
                rsum[i][0] += __expf(d[0] - mv0) + __expf(d[1] - mv0);
                rsum[i][1] += __expf(d[2] - mv1) + __expf(d[3] - mv1);
            }
        }
#pragma unroll
        for (int i = 0; i < 2; i++)
#pragma unroll
            for (int s = 0; s < 2; s++) {
                float v = rsum[i][s];
                v += __shfl_xor_sync(0xFFFFFFFFu, v, 1);
                v += __shfl_xor_sync(0xFFFFFFFFu, v, 2);
                rsum[i][s] = v;
            }
        if ((lid & 3) == 0) {
#pragma unroll
            for (int i = 0; i < 2; i++)
#pragma unroll
                for (int s = 0; s < 2; s++)
                    ps[wn * 128 + wm * 32 + i * 16 + (lid >> 2) + s * 8] = rsum[i][s];
        }
        __syncthreads();
        if (tid < 128) {
            long rg = (long)z * SQ_ + m0 + tid;
            gmax[rg * NTILES_ + blockIdx.x] = cm[tid];
            gsum[rg * NTILES_ + blockIdx.x] = ps[tid] + ps[128 + tid];
        }
        return;
    }

#pragma unroll
    for (int i = 0; i < 2; i++) {
#pragma unroll
        for (int f = 0; f < NF; f++) {
            const float* d = dc[i * NF + f];
            int rl = wm * 32 + i * 16 + (lid >> 2);
            int cl = wn * (NT / 2) + f * 8 + ((lid & 3) << 1);
            if (MODE == 0 || MODE == 2) {
                float bx = 0.0f, by = 0.0f;
                if (MODE == 0) { float2 bb = *(const float2*)(bias + n0 + cl); bx = bb.x; by = bb.y; }
                float v0 = d[0] + bx, v1 = d[1] + by;
                float v2 = d[2] + bx, v3 = d[3] + by;
                __nv_bfloat16 h0 = __float2bfloat16(v0), h1 = __float2bfloat16(v1);
                __nv_bfloat16 h2 = __float2bfloat16(v2), h3 = __float2bfloat16(v3);
                __nv_bfloat16* ch = (__nv_bfloat16*)Cp0;
                __nv_bfloat16* cll = (__nv_bfloat16*)Cp1;
                *(uint32_t*)(ch + (long)rl * LDC + cl)       = pk2(h0, h1);
                *(uint32_t*)(ch + (long)(rl + 8) * LDC + cl) = pk2(h2, h3);
                *(uint32_t*)(cll + (long)rl * LDC + cl) =
                    pk2(__float2bfloat16(v0 - __bfloat162float(h0)),
                        __float2bfloat16(v1 - __bfloat162float(h1)));
                *(uint32_t*)(cll + (long)(rl + 8) * LDC + cl) =
                    pk2(__float2bfloat16(v2 - __bfloat162float(h2)),
                        __float2bfloat16(v3 - __bfloat162float(h3)));
            } else {
                float2 bb = *(const float2*)(bias + n0 + cl);
                float* cp = (float*)Cp0;
                *(float2*)(cp + (long)rl * LDC + cl) =
                    make_float2(d[0] + bb.x, d[1] + bb.y);
                *(float2*)(cp + (long)(rl + 8) * LDC + cl) =
                    make_float2(d[2] + bb.x, d[3] + bb.y);
            }
        }
    }
}

// ---------------------------------------------------------------------------
// bf16 transpose: v h/l [b][kv][ch] -> vt h/l [b][ch][kv]
// ---------------------------------------------------------------------------
__global__ __launch_bounds__(256)
void transpose_bf16_kernel(const __nv_bfloat16* __restrict__ vh,
                           const __nv_bfloat16* __restrict__ vl,
                           __nv_bfloat16* __restrict__ vth,
                           __nv_bfloat16* __restrict__ vtl)
{
    __shared__ __nv_bfloat16 th[32][34], tl[32][34];
    const int b   = blockIdx.z;
    const int kv0 = blockIdx.x * 32, ch0 = blockIdx.y * 32;
    const int x = threadIdx.x, y = threadIdx.y;      // 32 x 8
#pragma unroll
    for (int i = y; i < 32; i += 8) {
        long src = ((long)b * SKV_ + kv0 + i) * DQ_ + ch0 + x;
        th[i][x] = vh[src];
        tl[i][x] = vl[src];
    }
    __syncthreads();
#pragma unroll
    for (int i = y; i < 32; i += 8) {
        long dst = ((long)b * DQ_ + ch0 + i) * SKV_ + kv0 + x;
        vth[dst] = th[x][i];
        vtl[dst] = tl[x][i];
    }
}

// ---------------------------------------------------------------------------
// Launch
// ---------------------------------------------------------------------------
extern "C" void kernel_launch(void* const* d_in, const int* in_sizes, int n_in,
                              void* d_out, int out_size)
{
    (void)in_sizes; (void)n_in; (void)out_size;

    const float* Q   = (const float*)d_in[0];
    const float* K   = (const float*)d_in[1];
    const float* V   = (const float*)d_in[2];
    const void*  Msk = d_in[3];
    const float* Wq  = (const float*)d_in[4];
    const float* bq  = (const float*)d_in[5];
    const float* Wk  = (const float*)d_in[6];
    const float* bk  = (const float*)d_in[7];
    const float* Wv  = (const float*)d_in[8];
    const float* bv  = (const float*)d_in[9];
    const float* Wo  = (const float*)d_in[10];
    const float* bo  = (const float*)d_in[11];

    float* out = (float*)d_out;                       // [B,SQ,DOUT]
    float* Wt  = out + (size_t)B_ * SQ_ * DOUT_;      // [B,H,SQ,SKV]

    __nv_bfloat16 *sqh, *sql, *skh, *skl, *svh, *svl;
    __nv_bfloat16 *wqh, *wql, *wkh, *wkl, *wvh, *wvl, *woh, *wol;
    __nv_bfloat16 *qh, *ql, *kh, *kl, *vh, *vl, *vth, *vtl, *ath, *atl;
    unsigned char* mT;
    float *gmx, *gsm, *rM, *rI;
    cudaGetSymbolAddress((void**)&sqh, g_sqh); cudaGetSymbolAddress((void**)&sql, g_sql);
    cudaGetSymbolAddress((void**)&skh, g_skh); cudaGetSymbolAddress((void**)&skl, g_skl);
    cudaGetSymbolAddress((void**)&svh, g_svh); cudaGetSymbolAddress((void**)&svl, g_svl);
    cudaGetSymbolAddress((void**)&wqh, g_wqh); cudaGetSymbolAddress((void**)&wql, g_wql);
    cudaGetSymbolAddress((void**)&wkh, g_wkh); cudaGetSymbolAddress((void**)&wkl, g_wkl);
    cudaGetSymbolAddress((void**)&wvh, g_wvh); cudaGetSymbolAddress((void**)&wvl, g_wvl);
    cudaGetSymbolAddress((void**)&woh, g_woh); cudaGetSymbolAddress((void**)&wol, g_wol);
    cudaGetSymbolAddress((void**)&qh,  g_qh);  cudaGetSymbolAddress((void**)&ql,  g_ql);
    cudaGetSymbolAddress((void**)&kh,  g_kh);  cudaGetSymbolAddress((void**)&kl,  g_kl);
    cudaGetSymbolAddress((void**)&vh,  g_vh);  cudaGetSymbolAddress((void**)&vl,  g_vl);
    cudaGetSymbolAddress((void**)&vth, g_vth); cudaGetSymbolAddress((void**)&vtl, g_vtl);
    cudaGetSymbolAddress((void**)&ath, g_ath); cudaGetSymbolAddress((void**)&atl, g_atl);
    cudaGetSymbolAddress((void**)&mT,  g_maskT);
    cudaGetSymbolAddress((void**)&gmx, g_gmax); cudaGetSymbolAddress((void**)&gsm, g_gsum);
    cudaGetSymbolAddress((void**)&rM,  g_rowM); cudaGetSymbolAddress((void**)&rI,  g_rowI);

    const int SMG = 2 * 49152;            // 98304: modes 0,2,3 (2 CTAs/SM)
    const int SM1 = 8192 + 49152;         // 57344: mode 1 (mask + 1-stage)
    cudaFuncSetAttribute(hgemm_kernel<0>, cudaFuncAttributeMaxDynamicSharedMemorySize, SMG);
    cudaFuncSetAttribute(hgemm_kernel<1>, cudaFuncAttributeMaxDynamicSharedMemorySize, SM1);
    cudaFuncSetAttribute(hgemm_kernel<2>, cudaFuncAttributeMaxDynamicSharedMemorySize, SMG);
    cudaFuncSetAttribute(hgemm_kernel<3>, cudaFuncAttributeMaxDynamicSharedMemorySize, SMG);

    // 0) probe + operand splits + mask transpose
    probe_mask_kernel<<<1, 1>>>((const unsigned int*)Msk);
    split_kernel<<<(B_ * SQ_ * DQ_)   / 1024, 256>>>(Q,  sqh, sql);
    split_kernel<<<(B_ * SKV_ * DKV_) / 1024, 256>>>(K, skh, skl);
    split_kernel<<<(B_ * SKV_ * DKV_) / 1024, 256>>>(V, svh, svl);
    split_kernel<<<(DQ_ * DQ_)   / 1024, 256>>>(Wq, wqh, wql);
    split_kernel<<<(DQ_ * DKV_)  / 1024, 256>>>(Wk, wkh, wkl);
    split_kernel<<<(DQ_ * DKV_)  / 1024, 256>>>(Wv, wvh, wvl);
    split_kernel<<<(DOUT_ * DQ_) / 1024, 256>>>(Wo, woh, wol);
    transpose_mask_kernel<<<dim3(SKV_ / 32, SQ_ / 32, B_), dim3(32, 8)>>>(Msk, mT);

    // 1) projections -> bf16 h/l
    hgemm_kernel<0><<<dim3(DQ_ / 64, (B_ * SQ_) / 128, 1), 256, SMG>>>(
        sqh, sql, nullptr, DQ_, wqh, wql, DQ_, bq, qh, ql, DQ_, DQ_,
        nullptr, nullptr, nullptr, nullptr, nullptr, nullptr);
    hgemm_kernel<0><<<dim3(DQ_ / 64, (B_ * SKV_) / 128, 1), 256, SMG>>>(
        skh, skl, nullptr, DKV_, wkh, wkl, DKV_, bk, kh, kl, DQ_, DKV_,
        nullptr, nullptr, nullptr, nullptr, nullptr, nullptr);
    hgemm_kernel<0><<<dim3(DQ_ / 64, (B_ * SKV_) / 128, 1), 256, SMG>>>(
        svh, svl, nullptr, DKV_, wvh, wvl, DKV_, bv, vh, vl, DQ_, DKV_,
        nullptr, nullptr, nullptr, nullptr, nullptr, nullptr);

    // 1b) transpose projected V (bf16 h/l)
    transpose_bf16_kernel<<<dim3(SKV_ / 32, DQ_ / 32, B_), dim3(32, 8)>>>(
        vh, vl, vth, vtl);

    // 2) masked scores -> fp32 Wt + per-tile softmax stats
    hgemm_kernel<1><<<dim3(SKV_ / 64, SQ_ / 128, B_ * H_), 256, SM1>>>(
        qh, ql, nullptr, 0, kh, kl, 0, nullptr, Wt, nullptr, 0, DH_,
        mT, gmx, gsm, nullptr, nullptr, nullptr);

    // 3) fold tile stats -> per-row (M, 1/S)
    stats_combine_kernel<<<NROWS_ / 8, 256>>>(gmx, gsm, rM, rI);

    // 4) PV: exp-normalize Wt inline (writeback normalized weights), GEMM with V^T
    hgemm_kernel<2><<<dim3(1, SQ_ / 128, B_ * H_), 256, SMG>>>(
        nullptr, nullptr, Wt, 0, vth, vtl, 0, nullptr, ath, atl, 0, SKV_,
        nullptr, nullptr, nullptr, rM, rI, Wt);

    // 5) output projection -> fp32 front of d_out
    hgemm_kernel<3><<<dim3(DOUT_ / 64, (B_ * SQ_) / 128, 1), 256, SMG>>>(
        ath, atl, nullptr, DQ_, woh, wol, DQ_, bo, out, nullptr, DOUT_, DQ_,
        nullptr, nullptr, nullptr, nullptr, nullptr, nullptr);
}